// round 13
// baseline (speedup 1.0000x reference)
#include <cuda_runtime.h>
#include <cuda_fp16.h>
#include <math.h>
#include <stdint.h>

#define BATCH 4
#define SEQ   4096
#define DIM   512
#define MTOT  (BATCH * SEQ)
#define NTILE (SEQ / 128)
#define WSZ   (DIM * DIM)
#define NEG_INF __int_as_float(0xff800000)

// ---------------- scratch (static device globals; no allocation) ------------
__device__ __half g_Xh[(size_t)MTOT * DIM],  g_Xl[(size_t)MTOT * DIM];
__device__ __half g_Wh[3][WSZ],              g_Wl[3][WSZ];
__device__ __half g_Qh[(size_t)MTOT * DIM],  g_Ql[(size_t)MTOT * DIM];
__device__ __half g_Kh[(size_t)MTOT * DIM],  g_Kl[(size_t)MTOT * DIM];
__device__ __half g_Vth[(size_t)DIM * MTOT];               // V^T hi plane only
__device__ __half g_E [(size_t)BATCH * SEQ * SEQ];         // exp(S - m_tile), fp16
__device__ float  g_cm[(size_t)NTILE * BATCH * SEQ];       // per-tile col max
__device__ float  g_cz[(size_t)NTILE * BATCH * SEQ];       // per-tile col sumexp
__device__ __half g_f [(size_t)BATCH * NTILE * SEQ];       // exp(m_tile-m)/Z
__device__ int    g_cnt[BATCH * NTILE];                    // column-group tickets

// ---------------- fast exp on the FMA pipe -----------------------------------
__device__ __forceinline__ float fast_exp(float x) {
    x = fmaxf(x, -80.0f);
    const float y  = x * 1.4426950408889634f;
    const float t  = y + 12582912.0f;
    const int   ni = __float_as_int(t) - 0x4B400000;
    const float f  = y - (t - 12582912.0f);
    float p = 1.3333558146e-3f;
    p = fmaf(p, f, 9.6181291076e-3f);
    p = fmaf(p, f, 5.5504108664e-2f);
    p = fmaf(p, f, 2.4022650696e-1f);
    p = fmaf(p, f, 6.9314718056e-1f);
    p = fmaf(p, f, 1.0f);
    return __int_as_float(__float_as_int(p) + (ni << 23));
}

// ============================ PTX helpers ===================================
__device__ __forceinline__ uint32_t smem_u32(const void* p) {
    uint32_t a;
    asm("{ .reg .u64 t; cvta.to.shared.u64 t, %1; cvt.u32.u64 %0, t; }"
        : "=r"(a) : "l"(p));
    return a;
}
template<int N> __device__ __forceinline__ void cp_wait() {
    asm volatile("cp.async.wait_group %0;" :: "n"(N) : "memory");
}
__device__ __forceinline__ void cp_commit() {
    asm volatile("cp.async.commit_group;" ::: "memory");
}
__device__ __forceinline__ void cp16(uint32_t dst, const void* src) {
    asm volatile("cp.async.cg.shared.global [%0], [%1], 16;"
                 :: "r"(dst), "l"(src) : "memory");
}
__device__ __forceinline__ void ldsm4(uint32_t* r, uint32_t a) {
    asm volatile("ldmatrix.sync.aligned.m8n8.x4.shared.b16 {%0,%1,%2,%3}, [%4];"
                 : "=r"(r[0]), "=r"(r[1]), "=r"(r[2]), "=r"(r[3]) : "r"(a));
}
__device__ __forceinline__ void mma16816(float* d, const uint32_t* a,
                                         uint32_t b0, uint32_t b1) {
    asm volatile("mma.sync.aligned.m16n8k16.row.col.f32.f16.f16.f32 "
                 "{%0,%1,%2,%3},{%4,%5,%6,%7},{%8,%9},{%0,%1,%2,%3};"
                 : "+f"(d[0]), "+f"(d[1]), "+f"(d[2]), "+f"(d[3])
                 : "r"(a[0]), "r"(a[1]), "r"(a[2]), "r"(a[3]), "r"(b0), "r"(b1));
}
__device__ __forceinline__ uint32_t hmul2u(uint32_t a, uint32_t b) {
    const __half2 r = __hmul2(*(const __half2*)&a, *(const __half2*)&b);
    return *(const uint32_t*)&r;
}

// ============================ GEMM (hi/lo fp16) ==============================
// C[m,n] = sum_k A[m,k]*B[n,k];  MT = m-tile (64 or 128), n-tile fixed 128
// ALO/BLO: lo planes exist. MMAs: AhBh [+AlBh if ALO] [+AhBl if BLO]
// PVF: multiply A-fragments by fp16 factor table f[k] (smem)
// EPI 0: fp32 C[m][n]                                            (PV, MT=64)
// EPI 3: fp16 E' + stats + fused f-combine via ticket            (S, MT=128)
// EPI 4: fused QKV: z selects W plane/bias; z<2 hi/lo, z=2 V^T   (MT=64)
#define TCT 256

template<int EPI, int ALO, int BLO, int PVF, int MT>
__global__ void __launch_bounds__(TCT, 2)
gemm_hl(const __half* __restrict__ Ah, const __half* __restrict__ Al,
        const __half* __restrict__ Bh, const __half* __restrict__ Bl,
        const float* __restrict__ bias0, const float* __restrict__ bias1,
        const float* __restrict__ bias2,
        float* __restrict__ C, __half* __restrict__ Eh,
        const __half* __restrict__ fTab,
        int K, int lda, int ldb, int ldc,
        long sA, long sB, long sC)
{
    constexpr int A_BYTES = MT * 64;
    constexpr int OFF_AL  = A_BYTES;
    constexpr int OFF_BH  = A_BYTES * (1 + ALO);
    constexpr int OFF_BL  = OFF_BH + 8192;
    constexpr int STG     = A_BYTES * (1 + ALO) + 8192 * (1 + BLO);
    constexpr int OFF_F   = 2 * STG;
    constexpr int MF      = MT / 32;

    extern __shared__ __align__(128) char smem[];
    const uint32_t sb = smem_u32(smem);

    const int tid = threadIdx.x;
    const int lid = tid & 31;
    const int wid = tid >> 5;
    const int wm  = wid >> 2;
    const int wn  = wid & 3;

    const long z = blockIdx.z;
    const float* bias = bias0;
    if (EPI == 4) {
        Bh += z * WSZ; if (BLO) Bl += z * WSZ;
        bias = (z == 0) ? bias0 : (z == 1) ? bias1 : bias2;
    } else {
        Ah += z * sA; if (ALO) Al += z * sA;
        Bh += z * sB; if (BLO) Bl += z * sB;
        if (EPI == 3) Eh += z * sC; else C += z * sC;
    }

    const int m0 = blockIdx.y * MT;
    const int n0 = blockIdx.x * 128;

    // preload f row for this (batch, 128-row q-tile) into smem
    if (PVF) {
        const __half* fB = fTab + ((size_t)blockIdx.z * NTILE + (blockIdx.y * MT / 128)) * SEQ;
#pragma unroll
        for (int i = 0; i < 2; i++) {
            const int c = i * 256 + tid;
            *(uint4*)(smem + OFF_F + c * 16) = *(const uint4*)(fB + c * 8);
        }
    }

    const int nstage = K / 32;

    auto issue = [&](int s) {
        const uint32_t base = sb + (s & 1) * STG;
        const int k0 = s * 32;
#pragma unroll
        for (int i = 0; i < MT / 64; i++) {
            const int chunk = i * 256 + tid;
            const int r = chunk >> 2;
            const int c = chunk & 3;
            const uint32_t doff = r * 64 + ((c ^ ((r + (r >> 2)) & 3)) * 16);
            const size_t ga = (size_t)(m0 + r) * lda + k0 + c * 8;
            cp16(base + doff, Ah + ga);
            if (ALO) cp16(base + OFF_AL + doff, Al + ga);
        }
#pragma unroll
        for (int i = 0; i < 2; i++) {
            const int chunk = i * 256 + tid;
            const int r = chunk >> 2;
            const int c = chunk & 3;
            const uint32_t doff = r * 64 + ((c ^ ((r + (r >> 2)) & 3)) * 16);
            const size_t gb = (size_t)(n0 + r) * ldb + k0 + c * 8;
            cp16(base + OFF_BH + doff, Bh + gb);
            if (BLO) cp16(base + OFF_BL + doff, Bl + gb);
        }
        cp_commit();
    };

    float acc[MF][4][4];
#pragma unroll
    for (int a = 0; a < MF; a++)
#pragma unroll
        for (int b = 0; b < 4; b++)
#pragma unroll
            for (int c = 0; c < 4; c++) acc[a][b][c] = 0.f;

    const int sub   = lid >> 3;
    const int lane7 = lid & 7;
    const int rA = wm * (MT / 2) + (sub & 1) * 8 + lane7;
    const int rB = wn * 32 + (sub & 1) * 8 + lane7;
    const int cs = sub >> 1;
    const int swA = (rA + (rA >> 2)) & 3;
    const int swB = (rB + (rB >> 2)) & 3;

    issue(0);
    issue(1);

    for (int s = 0; s < nstage; s++) {
        if (s + 1 < nstage) cp_wait<1>(); else cp_wait<0>();
        __syncthreads();

        const uint32_t stg = sb + (s & 1) * STG;
#pragma unroll
        for (int kt = 0; kt < 2; kt++) {
            const int ch = 2 * kt + cs;
            const uint32_t aoff = ((ch ^ swA) * 16);
            const uint32_t boff = ((ch ^ swB) * 16);

            uint32_t aH[MF][4], bH[2][4];
#pragma unroll
            for (int mf = 0; mf < MF; mf++)
                ldsm4(aH[mf], stg + (rA + mf * 16) * 64 + aoff);
#pragma unroll
            for (int bg = 0; bg < 2; bg++)
                ldsm4(bH[bg], stg + OFF_BH + (rB + bg * 16) * 64 + boff);

            if (PVF) {
                const int kb = s * 32 + kt * 16 + (lid & 3) * 2;
                const uint32_t flo = *(const uint32_t*)(smem + OFF_F + kb * 2);
                const uint32_t fhi = *(const uint32_t*)(smem + OFF_F + kb * 2 + 16);
#pragma unroll
                for (int mf = 0; mf < MF; mf++) {
                    aH[mf][0] = hmul2u(aH[mf][0], flo);
                    aH[mf][1] = hmul2u(aH[mf][1], flo);
                    aH[mf][2] = hmul2u(aH[mf][2], fhi);
                    aH[mf][3] = hmul2u(aH[mf][3], fhi);
                }
            }

            // hi * hi
#pragma unroll
            for (int mf = 0; mf < MF; mf++)
#pragma unroll
                for (int nf = 0; nf < 4; nf++)
                    mma16816(acc[mf][nf], aH[mf],
                             bH[nf >> 1][nf & 1], bH[nf >> 1][(nf & 1) + 2]);

            // lo * hi
            if (ALO) {
                uint32_t aL[MF][4];
#pragma unroll
                for (int mf = 0; mf < MF; mf++)
                    ldsm4(aL[mf], stg + OFF_AL + (rA + mf * 16) * 64 + aoff);
#pragma unroll
                for (int mf = 0; mf < MF; mf++)
#pragma unroll
                    for (int nf = 0; nf < 4; nf++)
                        mma16816(acc[mf][nf], aL[mf],
                                 bH[nf >> 1][nf & 1], bH[nf >> 1][(nf & 1) + 2]);
            }

            // hi * lo
            if (BLO) {
                uint32_t bL[2][4];
#pragma unroll
                for (int bg = 0; bg < 2; bg++)
                    ldsm4(bL[bg], stg + OFF_BL + (rB + bg * 16) * 64 + boff);
#pragma unroll
                for (int mf = 0; mf < MF; mf++)
#pragma unroll
                    for (int nf = 0; nf < 4; nf++)
                        mma16816(acc[mf][nf], aH[mf],
                                 bL[nf >> 1][nf & 1], bL[nf >> 1][(nf & 1) + 2]);
            }
        }

        if (s + 2 < nstage) {
            __syncthreads();
            issue(s + 2);
        }
    }

    // -------------------------- epilogue ------------------------------------
    if (EPI == 3) {
        // fused column softmax: per-tile col stats + E' = exp(acc - m_col) fp16
        __syncthreads();
        float* st = (float*)smem;           // [2][128][2] = 2KB

        float cm[8], cz[8];
#pragma unroll
        for (int nf = 0; nf < 4; nf++) {
#pragma unroll
            for (int e = 0; e < 2; e++) {
                float mx = NEG_INF;
#pragma unroll
                for (int mf = 0; mf < MF; mf++) {
                    mx = fmaxf(mx, acc[mf][nf][e]);
                    mx = fmaxf(mx, acc[mf][nf][e + 2]);
                }
                float zz = 0.f;
#pragma unroll
                for (int mf = 0; mf < MF; mf++)
                    zz += fast_exp(acc[mf][nf][e] - mx) + fast_exp(acc[mf][nf][e + 2] - mx);
                cm[nf * 2 + e] = mx;
                cz[nf * 2 + e] = zz;
            }
        }
#pragma unroll
        for (int off = 4; off < 32; off <<= 1) {
#pragma unroll
            for (int c = 0; c < 8; c++) {
                const float om = __shfl_xor_sync(0xffffffff, cm[c], off);
                const float oz = __shfl_xor_sync(0xffffffff, cz[c], off);
                const float mn = fmaxf(cm[c], om);
                cz[c] = cz[c] * fast_exp(cm[c] - mn) + oz * fast_exp(om - mn);
                cm[c] = mn;
            }
        }
        if ((lid >> 2) == 0) {
#pragma unroll
            for (int nf = 0; nf < 4; nf++)
#pragma unroll
                for (int e = 0; e < 2; e++) {
                    const int col = wn * 32 + nf * 8 + (lid & 3) * 2 + e;
                    st[(wm * 128 + col) * 2 + 0] = cm[nf * 2 + e];
                    st[(wm * 128 + col) * 2 + 1] = cz[nf * 2 + e];
                }
        }
        __syncthreads();

        // merged (128-row) column max for E'
        float mcol[8];
#pragma unroll
        for (int nf = 0; nf < 4; nf++)
#pragma unroll
            for (int e = 0; e < 2; e++) {
                const int col = wn * 32 + nf * 8 + (lid & 3) * 2 + e;
                mcol[nf * 2 + e] = fmaxf(st[col * 2], st[(128 + col) * 2]);
            }

#pragma unroll
        for (int mf = 0; mf < MF; mf++) {
#pragma unroll
            for (int nf = 0; nf < 4; nf++) {
                const int m = m0 + wm * (MT / 2) + mf * 16 + (lid >> 2);
                const int n = n0 + wn * 32 + nf * 8 + (lid & 3) * 2;
                const float m0c = mcol[nf * 2], m1c = mcol[nf * 2 + 1];
                const __half e0 = __float2half_rn(fast_exp(acc[mf][nf][0] - m0c));
                const __half e1 = __float2half_rn(fast_exp(acc[mf][nf][1] - m1c));
                const __half e2 = __float2half_rn(fast_exp(acc[mf][nf][2] - m0c));
                const __half e3 = __float2half_rn(fast_exp(acc[mf][nf][3] - m1c));
                *(__half2*)(Eh + (size_t)m * ldc + n)       = __halves2half2(e0, e1);
                *(__half2*)(Eh + (size_t)(m + 8) * ldc + n) = __halves2half2(e2, e3);
            }
        }

        if (tid < 128) {
            const float m0v = st[tid * 2],         z0v = st[tid * 2 + 1];
            const float m1v = st[(128 + tid) * 2], z1v = st[(128 + tid) * 2 + 1];
            const float mn = fmaxf(m0v, m1v);
            const float zz = z0v * fast_exp(m0v - mn) + z1v * fast_exp(m1v - mn);
            const size_t o = ((size_t)blockIdx.y * BATCH + blockIdx.z) * SEQ + n0 + tid;
            g_cm[o] = mn;
            g_cz[o] = zz;
        }

        // ---- fused f-combine: last CTA of this column group computes f ----
        __threadfence();                    // release stats before ticket
        __syncthreads();
        __shared__ int s_last;
        if (tid == 0) {
            const int grp = blockIdx.z * NTILE + blockIdx.x;
            s_last = (atomicAdd(&g_cnt[grp], 1) == NTILE - 1) ? 1 : 0;
        }
        __syncthreads();
        if (s_last && tid < 128) {
            __threadfence();                // acquire other CTAs' stats
            const int k = n0 + tid;
            const int b = blockIdx.z;
            float m = NEG_INF;
#pragma unroll
            for (int t = 0; t < NTILE; t++)
                m = fmaxf(m, __ldcg(&g_cm[((size_t)t * BATCH + b) * SEQ + k]));
            float zz = 0.f;
#pragma unroll
            for (int t = 0; t < NTILE; t++) {
                const size_t o = ((size_t)t * BATCH + b) * SEQ + k;
                zz += __ldcg(&g_cz[o]) * fast_exp(__ldcg(&g_cm[o]) - m);
            }
            const float rz = 1.0f / zz;
#pragma unroll
            for (int t = 0; t < NTILE; t++) {
                const size_t o = ((size_t)t * BATCH + b) * SEQ + k;
                g_f[((size_t)b * NTILE + t) * SEQ + k] =
                    __float2half_rn(fast_exp(__ldcg(&g_cm[o]) - m) * rz);
            }
        }
        return;
    }

#pragma unroll
    for (int mf = 0; mf < MF; mf++) {
#pragma unroll
        for (int nf = 0; nf < 4; nf++) {
            const int m = m0 + wm * (MT / 2) + mf * 16 + (lid >> 2);
            const int n = n0 + wn * 32 + nf * 8 + (lid & 3) * 2;
            float v0 = acc[mf][nf][0], v1 = acc[mf][nf][1];
            float v2 = acc[mf][nf][2], v3 = acc[mf][nf][3];
            if (EPI == 4) {
                const float b0 = bias[n], b1 = bias[n + 1];
                v0 += b0; v1 += b1; v2 += b0; v3 += b1;
            }
            if (EPI == 0) {
                *(float2*)(C + (size_t)m * ldc + n)       = make_float2(v0, v1);
                *(float2*)(C + (size_t)(m + 8) * ldc + n) = make_float2(v2, v3);
            } else {  // EPI 4
                const __half h0 = __float2half_rn(v0), h1 = __float2half_rn(v1);
                const __half h2 = __float2half_rn(v2), h3 = __float2half_rn(v3);
                if (z < 2) {
                    __half* Ch = (z == 0) ? g_Qh : g_Kh;
                    __half* Cl = (z == 0) ? g_Ql : g_Kl;
                    const __half l0 = __float2half_rn(v0 - __half2float(h0));
                    const __half l1 = __float2half_rn(v1 - __half2float(h1));
                    const __half l2 = __float2half_rn(v2 - __half2float(h2));
                    const __half l3 = __float2half_rn(v3 - __half2float(h3));
                    *(__half2*)(Ch + (size_t)m * DIM + n)       = __halves2half2(h0, h1);
                    *(__half2*)(Ch + (size_t)(m + 8) * DIM + n) = __halves2half2(h2, h3);
                    *(__half2*)(Cl + (size_t)m * DIM + n)       = __halves2half2(l0, l1);
                    *(__half2*)(Cl + (size_t)(m + 8) * DIM + n) = __halves2half2(l2, l3);
                } else {
                    g_Vth[(size_t)n * MTOT + m]           = h0;
                    g_Vth[(size_t)(n + 1) * MTOT + m]     = h1;
                    g_Vth[(size_t)n * MTOT + m + 8]       = h2;
                    g_Vth[(size_t)(n + 1) * MTOT + m + 8] = h3;
                }
            }
        }
    }
}

// ---------------------------------------------------------------------------
// One fused split pass: X then Wq, Wk, Wv; block 0 also resets tickets.
#define XN4 (MTOT * DIM / 4)
#define WN4 (WSZ / 4)

__global__ void __launch_bounds__(256)
split_all(const float* __restrict__ X, const float* __restrict__ Wq,
          const float* __restrict__ Wk, const float* __restrict__ Wv)
{
    if (blockIdx.x == 0 && threadIdx.x < BATCH * NTILE)
        g_cnt[threadIdx.x] = 0;

    const int i = blockIdx.x * 256 + threadIdx.x;
    const float* src;
    __half *h, *l;
    int j;
    if (i < XN4)                { src = X;  h = g_Xh;    l = g_Xl;    j = i; }
    else if (i < XN4 + WN4)     { src = Wq; h = g_Wh[0]; l = g_Wl[0]; j = i - XN4; }
    else if (i < XN4 + 2 * WN4) { src = Wk; h = g_Wh[1]; l = g_Wl[1]; j = i - XN4 - WN4; }
    else if (i < XN4 + 3 * WN4) { src = Wv; h = g_Wh[2]; l = g_Wl[2]; j = i - XN4 - 2 * WN4; }
    else return;

    const float4 v = ((const float4*)src)[j];
    float vv[4] = {v.x, v.y, v.z, v.w};
    __half hh[4], ll[4];
#pragma unroll
    for (int e = 0; e < 4; e++) {
        hh[e] = __float2half_rn(vv[e]);
        ll[e] = __float2half_rn(vv[e] - __half2float(hh[e]));
    }
    ((__half2*)h)[j * 2]     = __halves2half2(hh[0], hh[1]);
    ((__half2*)h)[j * 2 + 1] = __halves2half2(hh[2], hh[3]);
    ((__half2*)l)[j * 2]     = __halves2half2(ll[0], ll[1]);
    ((__half2*)l)[j * 2 + 1] = __halves2half2(ll[2], ll[3]);
}

// ---------------------------------------------------------------------------
extern "C" void kernel_launch(void* const* d_in, const int* in_sizes, int n_in,
                              void* d_out, int out_size)
{
    const float* X  = (const float*)d_in[0];
    const float* Wq = (const float*)d_in[1];
    const float* bq = (const float*)d_in[2];
    const float* Wk = (const float*)d_in[3];
    const float* bk = (const float*)d_in[4];
    const float* Wv = (const float*)d_in[5];
    const float* bv = (const float*)d_in[6];
    float* out = (float*)d_out;

    __half *pXh, *pXl, *pWh, *pWl, *pQh, *pQl, *pKh, *pKl, *pVth, *pE, *pF;
    cudaGetSymbolAddress((void**)&pXh,  g_Xh);
    cudaGetSymbolAddress((void**)&pXl,  g_Xl);
    cudaGetSymbolAddress((void**)&pWh,  g_Wh);
    cudaGetSymbolAddress((void**)&pWl,  g_Wl);
    cudaGetSymbolAddress((void**)&pQh,  g_Qh);
    cudaGetSymbolAddress((void**)&pQl,  g_Ql);
    cudaGetSymbolAddress((void**)&pKh,  g_Kh);
    cudaGetSymbolAddress((void**)&pKl,  g_Kl);
    cudaGetSymbolAddress((void**)&pVth, g_Vth);
    cudaGetSymbolAddress((void**)&pE,   g_E);
    cudaGetSymbolAddress((void**)&pF,   g_f);

    cudaFuncSetAttribute((const void*)gemm_hl<4,1,1,0,64>,  cudaFuncAttributeMaxDynamicSharedMemorySize, 49152);
    cudaFuncSetAttribute((const void*)gemm_hl<3,1,1,0,128>, cudaFuncAttributeMaxDynamicSharedMemorySize, 65536);
    cudaFuncSetAttribute((const void*)gemm_hl<0,0,0,1,64>,  cudaFuncAttributeMaxDynamicSharedMemorySize, 32768);

    const dim3 blk(TCT);

    // fused input splits (X + Wq + Wk + Wv) + ticket reset
    const int TOT4 = XN4 + 3 * WN4;
    split_all<<<(TOT4 + 255) / 256, 256>>>(X, Wq, Wk, Wv);

    // fused QKV projections (K=512): 64-row tiles, z selects q/k/v
    const dim3 gQKV(DIM / 128, MTOT / 64, 3);
    gemm_hl<4,1,1,0,64><<<gQKV, blk, 49152>>>(pXh, pXl, pWh, pWl, bq, bk, bv,
                                              nullptr, nullptr, nullptr,
                                              DIM, DIM, DIM, DIM, 0, 0, 0);

    // S-GEMM per batch (K=512): E' fp16 + stats + fused f-combine
    const dim3 gS(SEQ / 128, SEQ / 128, BATCH);
    gemm_hl<3,1,1,0,128><<<gS, blk, 65536>>>(pQh, pQl, pKh, pKl,
                                             nullptr, nullptr, nullptr,
                                             nullptr, pE, nullptr,
                                             DIM, DIM, DIM, SEQ,
                                             (long)SEQ * DIM, (long)SEQ * DIM,
                                             (long)SEQ * SEQ);

    // O = (E' * f) V per batch (K=4096): 64-row tiles, single MMA + f multiply
    const dim3 gPV(DIM / 128, SEQ / 64, BATCH);
    gemm_hl<0,0,0,1,64><<<gPV, blk, 32768>>>(pE, nullptr, pVth, nullptr,
                                             nullptr, nullptr, nullptr,
                                             out, nullptr, pF,
                                             SEQ, SEQ, MTOT, DIM,
                                             (long)SEQ * SEQ, SEQ, (long)SEQ * DIM);
}

// round 14
// speedup vs baseline: 1.0203x; 1.0203x over previous
#include <cuda_runtime.h>
#include <cuda_fp16.h>
#include <math.h>
#include <stdint.h>

#define BATCH 4
#define SEQ   4096
#define DIM   512
#define MTOT  (BATCH * SEQ)
#define NTILE (SEQ / 128)
#define WSZ   (DIM * DIM)
#define NEG_INF __int_as_float(0xff800000)

// ---------------- scratch (static device globals; no allocation) ------------
__device__ __half g_Xh[(size_t)MTOT * DIM],  g_Xl[(size_t)MTOT * DIM];
__device__ __half g_Wh[3][WSZ],              g_Wl[3][WSZ];
__device__ __half g_Qh[(size_t)MTOT * DIM],  g_Ql[(size_t)MTOT * DIM];
__device__ __half g_Kh[(size_t)MTOT * DIM],  g_Kl[(size_t)MTOT * DIM];
__device__ __half g_Vth[(size_t)DIM * MTOT];               // V^T hi plane only
__device__ __half g_E [(size_t)BATCH * SEQ * SEQ];         // exp(S - m_tile), fp16
__device__ float  g_cm[(size_t)NTILE * BATCH * SEQ];       // per-tile col max
__device__ float  g_cz[(size_t)NTILE * BATCH * SEQ];       // per-tile col sumexp
__device__ __half g_f [(size_t)BATCH * NTILE * SEQ];       // exp(m_tile-m)/Z
__device__ int    g_cnt[BATCH * NTILE];                    // column-group tickets

// ---------------- fast exp on the FMA pipe -----------------------------------
__device__ __forceinline__ float fast_exp(float x) {
    x = fmaxf(x, -80.0f);
    const float y  = x * 1.4426950408889634f;
    const float t  = y + 12582912.0f;
    const int   ni = __float_as_int(t) - 0x4B400000;
    const float f  = y - (t - 12582912.0f);
    float p = 1.3333558146e-3f;
    p = fmaf(p, f, 9.6181291076e-3f);
    p = fmaf(p, f, 5.5504108664e-2f);
    p = fmaf(p, f, 2.4022650696e-1f);
    p = fmaf(p, f, 6.9314718056e-1f);
    p = fmaf(p, f, 1.0f);
    return __int_as_float(__float_as_int(p) + (ni << 23));
}

// ============================ PTX helpers ===================================
__device__ __forceinline__ uint32_t smem_u32(const void* p) {
    uint32_t a;
    asm("{ .reg .u64 t; cvta.to.shared.u64 t, %1; cvt.u32.u64 %0, t; }"
        : "=r"(a) : "l"(p));
    return a;
}
template<int N> __device__ __forceinline__ void cp_wait() {
    asm volatile("cp.async.wait_group %0;" :: "n"(N) : "memory");
}
__device__ __forceinline__ void cp_commit() {
    asm volatile("cp.async.commit_group;" ::: "memory");
}
__device__ __forceinline__ void cp16(uint32_t dst, const void* src) {
    asm volatile("cp.async.cg.shared.global [%0], [%1], 16;"
                 :: "r"(dst), "l"(src) : "memory");
}
__device__ __forceinline__ void ldsm4(uint32_t* r, uint32_t a) {
    asm volatile("ldmatrix.sync.aligned.m8n8.x4.shared.b16 {%0,%1,%2,%3}, [%4];"
                 : "=r"(r[0]), "=r"(r[1]), "=r"(r[2]), "=r"(r[3]) : "r"(a));
}
__device__ __forceinline__ void mma16816(float* d, const uint32_t* a,
                                         uint32_t b0, uint32_t b1) {
    asm volatile("mma.sync.aligned.m16n8k16.row.col.f32.f16.f16.f32 "
                 "{%0,%1,%2,%3},{%4,%5,%6,%7},{%8,%9},{%0,%1,%2,%3};"
                 : "+f"(d[0]), "+f"(d[1]), "+f"(d[2]), "+f"(d[3])
                 : "r"(a[0]), "r"(a[1]), "r"(a[2]), "r"(a[3]), "r"(b0), "r"(b1));
}
__device__ __forceinline__ uint32_t hmul2u(uint32_t a, uint32_t b) {
    const __half2 r = __hmul2(*(const __half2*)&a, *(const __half2*)&b);
    return *(const uint32_t*)&r;
}

// ============================ GEMM (hi/lo fp16) ==============================
// C[m,n] = sum_k A[m,k]*B[n,k];  128x128 tiles
// ALO/BLO: lo planes exist. MMAs: AhBh [+AlBh if ALO] [+AhBl if BLO]
// PVF: multiply A-fragments by fp16 factor table f[k] (smem)
// EPI 0: fp32 C[m][n]                                            (PV)
// EPI 3: fp16 E' + stats + fused f-combine via ticket            (S)
// EPI 4: fused QKV: z selects W plane/bias; z<2 hi/lo, z=2 V^T
#define TCT 256

template<int EPI, int ALO, int BLO, int PVF>
__global__ void __launch_bounds__(TCT, 2)
gemm_hl(const __half* __restrict__ Ah, const __half* __restrict__ Al,
        const __half* __restrict__ Bh, const __half* __restrict__ Bl,
        const float* __restrict__ bias0, const float* __restrict__ bias1,
        const float* __restrict__ bias2,
        float* __restrict__ C, __half* __restrict__ Eh,
        const __half* __restrict__ fTab,
        int K, int lda, int ldb, int ldc,
        long sA, long sB, long sC)
{
    constexpr int OFF_AL = 8192;
    constexpr int OFF_BH = ALO ? 16384 : 8192;
    constexpr int OFF_BL = OFF_BH + 8192;
    constexpr int STG    = 8192 * (2 + ALO + BLO);
    constexpr int OFF_F  = 2 * STG;            // f table after stage buffers

    extern __shared__ __align__(128) char smem[];
    const uint32_t sb = smem_u32(smem);

    const int tid = threadIdx.x;
    const int lid = tid & 31;
    const int wid = tid >> 5;
    const int wm  = wid >> 2;
    const int wn  = wid & 3;

    const long z = blockIdx.z;
    const float* bias = bias0;
    if (EPI == 4) {
        Bh += z * WSZ; if (BLO) Bl += z * WSZ;
        bias = (z == 0) ? bias0 : (z == 1) ? bias1 : bias2;
    } else {
        Ah += z * sA; if (ALO) Al += z * sA;
        Bh += z * sB; if (BLO) Bl += z * sB;
        if (EPI == 3) Eh += z * sC; else C += z * sC;
    }

    const int m0 = blockIdx.y * 128;
    const int n0 = blockIdx.x * 128;

    // preload f row for this (batch, q-tile) into smem
    if (PVF) {
        const __half* fB = fTab + ((size_t)blockIdx.z * NTILE + blockIdx.y) * SEQ;
#pragma unroll
        for (int i = 0; i < 2; i++) {
            const int c = i * 256 + tid;      // 512 x 8 halves
            *(uint4*)(smem + OFF_F + c * 16) = *(const uint4*)(fB + c * 8);
        }
    }

    const int nstage = K / 32;

    auto issue = [&](int s) {
        const uint32_t base = sb + (s & 1) * STG;
        const int k0 = s * 32;
#pragma unroll
        for (int i = 0; i < 2; i++) {
            const int chunk = i * 256 + tid;
            const int r = chunk >> 2;
            const int c = chunk & 3;
            const uint32_t doff = r * 64 + ((c ^ ((r + (r >> 2)) & 3)) * 16);
            const size_t ga = (size_t)(m0 + r) * lda + k0 + c * 8;
            const size_t gb = (size_t)(n0 + r) * ldb + k0 + c * 8;
            cp16(base + doff, Ah + ga);
            if (ALO) cp16(base + OFF_AL + doff, Al + ga);
            cp16(base + OFF_BH + doff, Bh + gb);
            if (BLO) cp16(base + OFF_BL + doff, Bl + gb);
        }
        cp_commit();
    };

    float acc[4][4][4];
#pragma unroll
    for (int a = 0; a < 4; a++)
#pragma unroll
        for (int b = 0; b < 4; b++)
#pragma unroll
            for (int c = 0; c < 4; c++) acc[a][b][c] = 0.f;

    const int sub   = lid >> 3;
    const int lane7 = lid & 7;
    const int rA = wm * 64 + (sub & 1) * 8 + lane7;
    const int rB = wn * 32 + (sub & 1) * 8 + lane7;
    const int cs = sub >> 1;
    const int swA = (rA + (rA >> 2)) & 3;
    const int swB = (rB + (rB >> 2)) & 3;

    issue(0);
    issue(1);

    for (int s = 0; s < nstage; s++) {
        if (s + 1 < nstage) cp_wait<1>(); else cp_wait<0>();
        __syncthreads();

        const uint32_t stg = sb + (s & 1) * STG;
#pragma unroll
        for (int kt = 0; kt < 2; kt++) {
            const int ch = 2 * kt + cs;
            const uint32_t aoff = ((ch ^ swA) * 16);
            const uint32_t boff = ((ch ^ swB) * 16);

            uint32_t aH[4][4], bH[2][4];
#pragma unroll
            for (int mf = 0; mf < 4; mf++)
                ldsm4(aH[mf], stg + (rA + mf * 16) * 64 + aoff);
#pragma unroll
            for (int bg = 0; bg < 2; bg++)
                ldsm4(bH[bg], stg + OFF_BH + (rB + bg * 16) * 64 + boff);

            if (PVF) {
                const int kb = s * 32 + kt * 16 + (lid & 3) * 2;
                const uint32_t flo = *(const uint32_t*)(smem + OFF_F + kb * 2);
                const uint32_t fhi = *(const uint32_t*)(smem + OFF_F + kb * 2 + 16);
#pragma unroll
                for (int mf = 0; mf < 4; mf++) {
                    aH[mf][0] = hmul2u(aH[mf][0], flo);
                    aH[mf][1] = hmul2u(aH[mf][1], flo);
                    aH[mf][2] = hmul2u(aH[mf][2], fhi);
                    aH[mf][3] = hmul2u(aH[mf][3], fhi);
                }
            }

            // hi * hi
#pragma unroll
            for (int mf = 0; mf < 4; mf++)
#pragma unroll
                for (int nf = 0; nf < 4; nf++)
                    mma16816(acc[mf][nf], aH[mf],
                             bH[nf >> 1][nf & 1], bH[nf >> 1][(nf & 1) + 2]);

            // lo * hi
            if (ALO) {
                uint32_t aL[4][4];
#pragma unroll
                for (int mf = 0; mf < 4; mf++)
                    ldsm4(aL[mf], stg + OFF_AL + (rA + mf * 16) * 64 + aoff);
#pragma unroll
                for (int mf = 0; mf < 4; mf++)
#pragma unroll
                    for (int nf = 0; nf < 4; nf++)
                        mma16816(acc[mf][nf], aL[mf],
                                 bH[nf >> 1][nf & 1], bH[nf >> 1][(nf & 1) + 2]);
            }

            // hi * lo
            if (BLO) {
                uint32_t bL[2][4];
#pragma unroll
                for (int bg = 0; bg < 2; bg++)
                    ldsm4(bL[bg], stg + OFF_BL + (rB + bg * 16) * 64 + boff);
#pragma unroll
                for (int mf = 0; mf < 4; mf++)
#pragma unroll
                    for (int nf = 0; nf < 4; nf++)
                        mma16816(acc[mf][nf], aH[mf],
                                 bL[nf >> 1][nf & 1], bL[nf >> 1][(nf & 1) + 2]);
            }
        }

        if (s + 2 < nstage) {
            __syncthreads();
            issue(s + 2);
        }
    }

    // -------------------------- epilogue ------------------------------------
    if (EPI == 3) {
        // fused column softmax: per-tile col stats + E' = exp(acc - m_col) fp16
        __syncthreads();
        float* st = (float*)smem;           // [2][128][2] = 2KB

        float cm[8], cz[8];
#pragma unroll
        for (int nf = 0; nf < 4; nf++) {
#pragma unroll
            for (int e = 0; e < 2; e++) {
                float mx = NEG_INF;
#pragma unroll
                for (int mf = 0; mf < 4; mf++) {
                    mx = fmaxf(mx, acc[mf][nf][e]);
                    mx = fmaxf(mx, acc[mf][nf][e + 2]);
                }
                float zz = 0.f;
#pragma unroll
                for (int mf = 0; mf < 4; mf++)
                    zz += fast_exp(acc[mf][nf][e] - mx) + fast_exp(acc[mf][nf][e + 2] - mx);
                cm[nf * 2 + e] = mx;
                cz[nf * 2 + e] = zz;
            }
        }
#pragma unroll
        for (int off = 4; off < 32; off <<= 1) {
#pragma unroll
            for (int c = 0; c < 8; c++) {
                const float om = __shfl_xor_sync(0xffffffff, cm[c], off);
                const float oz = __shfl_xor_sync(0xffffffff, cz[c], off);
                const float mn = fmaxf(cm[c], om);
                cz[c] = cz[c] * fast_exp(cm[c] - mn) + oz * fast_exp(om - mn);
                cm[c] = mn;
            }
        }
        if ((lid >> 2) == 0) {
#pragma unroll
            for (int nf = 0; nf < 4; nf++)
#pragma unroll
                for (int e = 0; e < 2; e++) {
                    const int col = wn * 32 + nf * 8 + (lid & 3) * 2 + e;
                    st[(wm * 128 + col) * 2 + 0] = cm[nf * 2 + e];
                    st[(wm * 128 + col) * 2 + 1] = cz[nf * 2 + e];
                }
        }
        __syncthreads();

        // merged (128-row) column max for E'
        float mcol[8];
#pragma unroll
        for (int nf = 0; nf < 4; nf++)
#pragma unroll
            for (int e = 0; e < 2; e++) {
                const int col = wn * 32 + nf * 8 + (lid & 3) * 2 + e;
                mcol[nf * 2 + e] = fmaxf(st[col * 2], st[(128 + col) * 2]);
            }

#pragma unroll
        for (int mf = 0; mf < 4; mf++) {
#pragma unroll
            for (int nf = 0; nf < 4; nf++) {
                const int m = m0 + wm * 64 + mf * 16 + (lid >> 2);
                const int n = n0 + wn * 32 + nf * 8 + (lid & 3) * 2;
                const float m0c = mcol[nf * 2], m1c = mcol[nf * 2 + 1];
                const __half e0 = __float2half_rn(fast_exp(acc[mf][nf][0] - m0c));
                const __half e1 = __float2half_rn(fast_exp(acc[mf][nf][1] - m1c));
                const __half e2 = __float2half_rn(fast_exp(acc[mf][nf][2] - m0c));
                const __half e3 = __float2half_rn(fast_exp(acc[mf][nf][3] - m1c));
                *(__half2*)(Eh + (size_t)m * ldc + n)       = __halves2half2(e0, e1);
                *(__half2*)(Eh + (size_t)(m + 8) * ldc + n) = __halves2half2(e2, e3);
            }
        }

        if (tid < 128) {
            const float m0v = st[tid * 2],         z0v = st[tid * 2 + 1];
            const float m1v = st[(128 + tid) * 2], z1v = st[(128 + tid) * 2 + 1];
            const float mn = fmaxf(m0v, m1v);
            const float zz = z0v * fast_exp(m0v - mn) + z1v * fast_exp(m1v - mn);
            const size_t o = ((size_t)blockIdx.y * BATCH + blockIdx.z) * SEQ + n0 + tid;
            g_cm[o] = mn;
            g_cz[o] = zz;
        }

        // ---- fused f-combine: last CTA of this column group computes f ----
        __threadfence();                    // release stats before ticket
        __syncthreads();
        __shared__ int s_last;
        if (tid == 0) {
            const int grp = blockIdx.z * NTILE + blockIdx.x;
            s_last = (atomicAdd(&g_cnt[grp], 1) == NTILE - 1) ? 1 : 0;
        }
        __syncthreads();
        if (s_last && tid < 128) {
            __threadfence();                // acquire other CTAs' stats
            const int k = n0 + tid;
            const int b = blockIdx.z;
            float m = NEG_INF;
#pragma unroll
            for (int t = 0; t < NTILE; t++)
                m = fmaxf(m, __ldcg(&g_cm[((size_t)t * BATCH + b) * SEQ + k]));
            float zz = 0.f;
#pragma unroll
            for (int t = 0; t < NTILE; t++) {
                const size_t o = ((size_t)t * BATCH + b) * SEQ + k;
                zz += __ldcg(&g_cz[o]) * fast_exp(__ldcg(&g_cm[o]) - m);
            }
            const float rz = 1.0f / zz;
#pragma unroll
            for (int t = 0; t < NTILE; t++) {
                const size_t o = ((size_t)t * BATCH + b) * SEQ + k;
                g_f[((size_t)b * NTILE + t) * SEQ + k] =
                    __float2half_rn(fast_exp(__ldcg(&g_cm[o]) - m) * rz);
            }
        }
        return;
    }

#pragma unroll
    for (int mf = 0; mf < 4; mf++) {
#pragma unroll
        for (int nf = 0; nf < 4; nf++) {
            const int m = m0 + wm * 64 + mf * 16 + (lid >> 2);
            const int n = n0 + wn * 32 + nf * 8 + (lid & 3) * 2;
            float v0 = acc[mf][nf][0], v1 = acc[mf][nf][1];
            float v2 = acc[mf][nf][2], v3 = acc[mf][nf][3];
            if (EPI == 4) {
                const float b0 = bias[n], b1 = bias[n + 1];
                v0 += b0; v1 += b1; v2 += b0; v3 += b1;
            }
            if (EPI == 0) {
                *(float2*)(C + (size_t)m * ldc + n)       = make_float2(v0, v1);
                *(float2*)(C + (size_t)(m + 8) * ldc + n) = make_float2(v2, v3);
            } else {  // EPI 4
                const __half h0 = __float2half_rn(v0), h1 = __float2half_rn(v1);
                const __half h2 = __float2half_rn(v2), h3 = __float2half_rn(v3);
                if (z < 2) {
                    __half* Ch = (z == 0) ? g_Qh : g_Kh;
                    __half* Cl = (z == 0) ? g_Ql : g_Kl;
                    const __half l0 = __float2half_rn(v0 - __half2float(h0));
                    const __half l1 = __float2half_rn(v1 - __half2float(h1));
                    const __half l2 = __float2half_rn(v2 - __half2float(h2));
                    const __half l3 = __float2half_rn(v3 - __half2float(h3));
                    *(__half2*)(Ch + (size_t)m * DIM + n)       = __halves2half2(h0, h1);
                    *(__half2*)(Ch + (size_t)(m + 8) * DIM + n) = __halves2half2(h2, h3);
                    *(__half2*)(Cl + (size_t)m * DIM + n)       = __halves2half2(l0, l1);
                    *(__half2*)(Cl + (size_t)(m + 8) * DIM + n) = __halves2half2(l2, l3);
                } else {
                    g_Vth[(size_t)n * MTOT + m]           = h0;
                    g_Vth[(size_t)(n + 1) * MTOT + m]     = h1;
                    g_Vth[(size_t)n * MTOT + m + 8]       = h2;
                    g_Vth[(size_t)(n + 1) * MTOT + m + 8] = h3;
                }
            }
        }
    }
}

// ---------------------------------------------------------------------------
// One fused split pass: X then Wq, Wk, Wv; block 0 also resets tickets.
#define XN4 (MTOT * DIM / 4)
#define WN4 (WSZ / 4)

__global__ void __launch_bounds__(256)
split_all(const float* __restrict__ X, const float* __restrict__ Wq,
          const float* __restrict__ Wk, const float* __restrict__ Wv)
{
    if (blockIdx.x == 0 && threadIdx.x < BATCH * NTILE)
        g_cnt[threadIdx.x] = 0;

    const int i = blockIdx.x * 256 + threadIdx.x;
    const float* src;
    __half *h, *l;
    int j;
    if (i < XN4)                { src = X;  h = g_Xh;    l = g_Xl;    j = i; }
    else if (i < XN4 + WN4)     { src = Wq; h = g_Wh[0]; l = g_Wl[0]; j = i - XN4; }
    else if (i < XN4 + 2 * WN4) { src = Wk; h = g_Wh[1]; l = g_Wl[1]; j = i - XN4 - WN4; }
    else if (i < XN4 + 3 * WN4) { src = Wv; h = g_Wh[2]; l = g_Wl[2]; j = i - XN4 - 2 * WN4; }
    else return;

    const float4 v = ((const float4*)src)[j];
    float vv[4] = {v.x, v.y, v.z, v.w};
    __half hh[4], ll[4];
#pragma unroll
    for (int e = 0; e < 4; e++) {
        hh[e] = __float2half_rn(vv[e]);
        ll[e] = __float2half_rn(vv[e] - __half2float(hh[e]));
    }
    ((__half2*)h)[j * 2]     = __halves2half2(hh[0], hh[1]);
    ((__half2*)h)[j * 2 + 1] = __halves2half2(hh[2], hh[3]);
    ((__half2*)l)[j * 2]     = __halves2half2(ll[0], ll[1]);
    ((__half2*)l)[j * 2 + 1] = __halves2half2(ll[2], ll[3]);
}

// ---------------------------------------------------------------------------
extern "C" void kernel_launch(void* const* d_in, const int* in_sizes, int n_in,
                              void* d_out, int out_size)
{
    const float* X  = (const float*)d_in[0];
    const float* Wq = (const float*)d_in[1];
    const float* bq = (const float*)d_in[2];
    const float* Wk = (const float*)d_in[3];
    const float* bk = (const float*)d_in[4];
    const float* Wv = (const float*)d_in[5];
    const float* bv = (const float*)d_in[6];
    float* out = (float*)d_out;

    __half *pXh, *pXl, *pWh, *pWl, *pQh, *pQl, *pKh, *pKl, *pVth, *pE, *pF;
    cudaGetSymbolAddress((void**)&pXh,  g_Xh);
    cudaGetSymbolAddress((void**)&pXl,  g_Xl);
    cudaGetSymbolAddress((void**)&pWh,  g_Wh);
    cudaGetSymbolAddress((void**)&pWl,  g_Wl);
    cudaGetSymbolAddress((void**)&pQh,  g_Qh);
    cudaGetSymbolAddress((void**)&pQl,  g_Ql);
    cudaGetSymbolAddress((void**)&pKh,  g_Kh);
    cudaGetSymbolAddress((void**)&pKl,  g_Kl);
    cudaGetSymbolAddress((void**)&pVth, g_Vth);
    cudaGetSymbolAddress((void**)&pE,   g_E);
    cudaGetSymbolAddress((void**)&pF,   g_f);

    cudaFuncSetAttribute((const void*)gemm_hl<4,1,1,0>, cudaFuncAttributeMaxDynamicSharedMemorySize, 65536);
    cudaFuncSetAttribute((const void*)gemm_hl<3,1,1,0>, cudaFuncAttributeMaxDynamicSharedMemorySize, 65536);
    cudaFuncSetAttribute((const void*)gemm_hl<0,0,0,1>, cudaFuncAttributeMaxDynamicSharedMemorySize, 40960);

    const dim3 blk(TCT);

    // fused input splits (X + Wq + Wk + Wv) + ticket reset
    const int TOT4 = XN4 + 3 * WN4;
    split_all<<<(TOT4 + 255) / 256, 256>>>(X, Wq, Wk, Wv);

    // fused QKV projections (K=512): one launch, z selects q/k/v
    const dim3 gQKV(DIM / 128, MTOT / 128, 3);
    gemm_hl<4,1,1,0><<<gQKV, blk, 65536>>>(pXh, pXl, pWh, pWl, bq, bk, bv,
                                           nullptr, nullptr, nullptr,
                                           DIM, DIM, DIM, DIM, 0, 0, 0);

    // S-GEMM per batch (K=512): E' fp16 + stats + fused f-combine
    const dim3 gS(SEQ / 128, SEQ / 128, BATCH);
    gemm_hl<3,1,1,0><<<gS, blk, 65536>>>(pQh, pQl, pKh, pKl,
                                         nullptr, nullptr, nullptr,
                                         nullptr, pE, nullptr,
                                         DIM, DIM, DIM, SEQ,
                                         (long)SEQ * DIM, (long)SEQ * DIM,
                                         (long)SEQ * SEQ);

    // O = (E' * f) V per batch (K=4096), single MMA + in-fragment f multiply
    const dim3 gPV(DIM / 128, SEQ / 128, BATCH);
    gemm_hl<0,0,0,1><<<gPV, blk, 40960>>>(pE, nullptr, pVth, nullptr,
                                          nullptr, nullptr, nullptr,
                                          out, nullptr, pF,
                                          SEQ, SEQ, MTOT, DIM,
                                          (long)SEQ * SEQ, SEQ, (long)SEQ * DIM);
}

// round 16
// speedup vs baseline: 1.1009x; 1.0790x over previous
#include <cuda_runtime.h>
#include <cuda_fp16.h>
#include <math.h>
#include <stdint.h>

#define BATCH 4
#define SEQ   4096
#define DIM   512
#define MTOT  (BATCH * SEQ)
#define NTILE (SEQ / 128)
#define WSZ   (DIM * DIM)
#define NEG_INF __int_as_float(0xff800000)

// ---------------- scratch (static device globals; no allocation) ------------
__device__ __half g_Xh[(size_t)MTOT * DIM],  g_Xl[(size_t)MTOT * DIM];
__device__ __half g_Wh[3][WSZ],              g_Wl[3][WSZ];
__device__ __half g_Qh[(size_t)MTOT * DIM],  g_Ql[(size_t)MTOT * DIM];
__device__ __half g_Kh[(size_t)MTOT * DIM],  g_Kl[(size_t)MTOT * DIM];
__device__ __half g_Vth[(size_t)DIM * MTOT];               // V^T hi plane only
__device__ __half g_E [(size_t)BATCH * SEQ * SEQ];         // exp(S - m_tile), fp16
__device__ float  g_cm[(size_t)NTILE * BATCH * SEQ];       // per-tile col max
__device__ float  g_cz[(size_t)NTILE * BATCH * SEQ];       // per-tile col sumexp
__device__ __half g_f [(size_t)BATCH * NTILE * SEQ];       // exp(m_tile-m)/Z
__device__ int    g_cnt[BATCH * NTILE];                    // column-group tickets

// ---------------- fast exp on the FMA pipe -----------------------------------
__device__ __forceinline__ float fast_exp(float x) {
    x = fmaxf(x, -80.0f);
    const float y  = x * 1.4426950408889634f;
    const float t  = y + 12582912.0f;
    const int   ni = __float_as_int(t) - 0x4B400000;
    const float f  = y - (t - 12582912.0f);
    float p = 1.3333558146e-3f;
    p = fmaf(p, f, 9.6181291076e-3f);
    p = fmaf(p, f, 5.5504108664e-2f);
    p = fmaf(p, f, 2.4022650696e-1f);
    p = fmaf(p, f, 6.9314718056e-1f);
    p = fmaf(p, f, 1.0f);
    return __int_as_float(__float_as_int(p) + (ni << 23));
}

// ============================ PTX helpers ===================================
__device__ __forceinline__ uint32_t smem_u32(const void* p) {
    uint32_t a;
    asm("{ .reg .u64 t; cvta.to.shared.u64 t, %1; cvt.u32.u64 %0, t; }"
        : "=r"(a) : "l"(p));
    return a;
}
template<int N> __device__ __forceinline__ void cp_wait() {
    asm volatile("cp.async.wait_group %0;" :: "n"(N) : "memory");
}
__device__ __forceinline__ void cp_commit() {
    asm volatile("cp.async.commit_group;" ::: "memory");
}
__device__ __forceinline__ void cp16(uint32_t dst, const void* src) {
    asm volatile("cp.async.cg.shared.global [%0], [%1], 16;"
                 :: "r"(dst), "l"(src) : "memory");
}
__device__ __forceinline__ void ldsm4(uint32_t* r, uint32_t a) {
    asm volatile("ldmatrix.sync.aligned.m8n8.x4.shared.b16 {%0,%1,%2,%3}, [%4];"
                 : "=r"(r[0]), "=r"(r[1]), "=r"(r[2]), "=r"(r[3]) : "r"(a));
}
__device__ __forceinline__ void mma16816(float* d, const uint32_t* a,
                                         uint32_t b0, uint32_t b1) {
    asm volatile("mma.sync.aligned.m16n8k16.row.col.f32.f16.f16.f32 "
                 "{%0,%1,%2,%3},{%4,%5,%6,%7},{%8,%9},{%0,%1,%2,%3};"
                 : "+f"(d[0]), "+f"(d[1]), "+f"(d[2]), "+f"(d[3])
                 : "r"(a[0]), "r"(a[1]), "r"(a[2]), "r"(a[3]), "r"(b0), "r"(b1));
}
__device__ __forceinline__ uint32_t hmul2u(uint32_t a, uint32_t b) {
    const __half2 r = __hmul2(*(const __half2*)&a, *(const __half2*)&b);
    return *(const uint32_t*)&r;
}

// ============================ GEMM (hi/lo fp16) ==============================
// C[m,n] = sum_k A[m,k]*B[n,k];  128x128 tiles; 3-stage ring, 1 sync/stage
// ALO/BLO: lo planes exist. MMAs: AhBh [+AlBh if ALO] [+AhBl if BLO]
// PVF: scale B-fragments by fp16 factor table f[k] (smem)
// EPI 0: fp32 C[m][n]                                            (PV)
// EPI 3: fp16 E' + stats + fused f-combine via ticket            (S)
// EPI 4: fused QKV: z selects W plane/bias; z<2 hi/lo, z=2 V^T
#define TCT 256

template<int EPI, int ALO, int BLO, int PVF>
__global__ void __launch_bounds__(TCT, 2)
gemm_hl(const __half* __restrict__ Ah, const __half* __restrict__ Al,
        const __half* __restrict__ Bh, const __half* __restrict__ Bl,
        const float* __restrict__ bias0, const float* __restrict__ bias1,
        const float* __restrict__ bias2,
        float* __restrict__ C, __half* __restrict__ Eh,
        const __half* __restrict__ fTab,
        int K, int lda, int ldb, int ldc,
        long sA, long sB, long sC)
{
    constexpr int OFF_AL = 8192;
    constexpr int OFF_BH = ALO ? 16384 : 8192;
    constexpr int OFF_BL = OFF_BH + 8192;
    constexpr int STG    = 8192 * (2 + ALO + BLO);
    constexpr int OFF_F  = 3 * STG;            // f table after 3 stage buffers

    extern __shared__ __align__(128) char smem[];
    const uint32_t sb = smem_u32(smem);

    const int tid = threadIdx.x;
    const int lid = tid & 31;
    const int wid = tid >> 5;
    const int wm  = wid >> 2;
    const int wn  = wid & 3;

    const long z = blockIdx.z;
    const float* bias = bias0;
    if (EPI == 4) {
        Bh += z * WSZ; if (BLO) Bl += z * WSZ;
        bias = (z == 0) ? bias0 : (z == 1) ? bias1 : bias2;
    } else {
        Ah += z * sA; if (ALO) Al += z * sA;
        Bh += z * sB; if (BLO) Bl += z * sB;
        if (EPI == 3) Eh += z * sC; else C += z * sC;
    }

    const int m0 = blockIdx.y * 128;
    const int n0 = blockIdx.x * 128;

    // preload f row for this (batch, q-tile) into smem (512 cols x 16B = 8KB)
    if (PVF) {
        const __half* fB = fTab + ((size_t)blockIdx.z * NTILE + blockIdx.y) * SEQ;
#pragma unroll
        for (int i = 0; i < 2; i++) {
            const int c = i * 256 + tid;
            *(uint4*)(smem + OFF_F + c * 16) = *(const uint4*)(fB + c * 8);
        }
    }

    const int nstage = K / 32;

    auto issue = [&](int s, int buf) {
        const uint32_t base = sb + buf * STG;
        const int k0 = s * 32;
#pragma unroll
        for (int i = 0; i < 2; i++) {
            const int chunk = i * 256 + tid;
            const int r = chunk >> 2;
            const int c = chunk & 3;
            const uint32_t doff = r * 64 + ((c ^ ((r + (r >> 2)) & 3)) * 16);
            const size_t ga = (size_t)(m0 + r) * lda + k0 + c * 8;
            const size_t gb = (size_t)(n0 + r) * ldb + k0 + c * 8;
            cp16(base + doff, Ah + ga);
            if (ALO) cp16(base + OFF_AL + doff, Al + ga);
            cp16(base + OFF_BH + doff, Bh + gb);
            if (BLO) cp16(base + OFF_BL + doff, Bl + gb);
        }
        cp_commit();
    };

    float acc[4][4][4];
#pragma unroll
    for (int a = 0; a < 4; a++)
#pragma unroll
        for (int b = 0; b < 4; b++)
#pragma unroll
            for (int c = 0; c < 4; c++) acc[a][b][c] = 0.f;

    const int sub   = lid >> 3;
    const int lane7 = lid & 7;
    const int rA = wm * 64 + (sub & 1) * 8 + lane7;
    const int rB = wn * 32 + (sub & 1) * 8 + lane7;
    const int cs = sub >> 1;
    const int swA = (rA + (rA >> 2)) & 3;
    const int swB = (rB + (rB >> 2)) & 3;

    issue(0, 0);
    issue(1, 1);

    int buf = 0;       // buffer of current stage s
    int nbuf = 2;      // buffer to fill with stage s+2
    for (int s = 0; s < nstage; s++) {
        if (s + 1 < nstage) cp_wait<1>(); else cp_wait<0>();
        __syncthreads();                    // stage s data visible; buf(s-1) free

        const uint32_t stg = sb + buf * STG;
#pragma unroll
        for (int kt = 0; kt < 2; kt++) {
            const int ch = 2 * kt + cs;
            const uint32_t aoff = ((ch ^ swA) * 16);
            const uint32_t boff = ((ch ^ swB) * 16);

            uint32_t aH[4][4], bH[2][4];
#pragma unroll
            for (int mf = 0; mf < 4; mf++)
                ldsm4(aH[mf], stg + (rA + mf * 16) * 64 + aoff);
#pragma unroll
            for (int bg = 0; bg < 2; bg++)
                ldsm4(bH[bg], stg + OFF_BH + (rB + bg * 16) * 64 + boff);

            if (PVF) {
                // scale B k-slices: regs {0,1} = k-lo pair, {2,3} = k-hi pair
                const int kb = s * 32 + kt * 16 + (lid & 3) * 2;
                const uint32_t flo = *(const uint32_t*)(smem + OFF_F + kb * 2);
                const uint32_t fhi = *(const uint32_t*)(smem + OFF_F + kb * 2 + 16);
#pragma unroll
                for (int bg = 0; bg < 2; bg++) {
                    bH[bg][0] = hmul2u(bH[bg][0], flo);
                    bH[bg][1] = hmul2u(bH[bg][1], flo);
                    bH[bg][2] = hmul2u(bH[bg][2], fhi);
                    bH[bg][3] = hmul2u(bH[bg][3], fhi);
                }
            }

            // hi * hi
#pragma unroll
            for (int mf = 0; mf < 4; mf++)
#pragma unroll
                for (int nf = 0; nf < 4; nf++)
                    mma16816(acc[mf][nf], aH[mf],
                             bH[nf >> 1][nf & 1], bH[nf >> 1][(nf & 1) + 2]);

            // lo * hi
            if (ALO) {
                uint32_t aL[4][4];
#pragma unroll
                for (int mf = 0; mf < 4; mf++)
                    ldsm4(aL[mf], stg + OFF_AL + (rA + mf * 16) * 64 + aoff);
#pragma unroll
                for (int mf = 0; mf < 4; mf++)
#pragma unroll
                    for (int nf = 0; nf < 4; nf++)
                        mma16816(acc[mf][nf], aL[mf],
                                 bH[nf >> 1][nf & 1], bH[nf >> 1][(nf & 1) + 2]);
            }

            // hi * lo
            if (BLO) {
                uint32_t bL[2][4];
#pragma unroll
                for (int bg = 0; bg < 2; bg++)
                    ldsm4(bL[bg], stg + OFF_BL + (rB + bg * 16) * 64 + boff);
#pragma unroll
                for (int mf = 0; mf < 4; mf++)
#pragma unroll
                    for (int nf = 0; nf < 4; nf++)
                        mma16816(acc[mf][nf], aH[mf],
                                 bL[nf >> 1][nf & 1], bL[nf >> 1][(nf & 1) + 2]);
            }
        }

        // refill buffer (s-1)%3 with stage s+2 (safe: freed by this stage's sync)
        if (s + 2 < nstage) issue(s + 2, nbuf);
        buf  = (buf  == 2) ? 0 : buf + 1;
        nbuf = (nbuf == 2) ? 0 : nbuf + 1;
    }

    // -------------------------- epilogue ------------------------------------
    if (EPI == 3) {
        __syncthreads();
        float* st = (float*)smem;           // [2][128][2] = 2KB

        float cm[8], cz[8];
#pragma unroll
        for (int nf = 0; nf < 4; nf++) {
#pragma unroll
            for (int e = 0; e < 2; e++) {
                float mx = NEG_INF;
#pragma unroll
                for (int mf = 0; mf < 4; mf++) {
                    mx = fmaxf(mx, acc[mf][nf][e]);
                    mx = fmaxf(mx, acc[mf][nf][e + 2]);
                }
                float zz = 0.f;
#pragma unroll
                for (int mf = 0; mf < 4; mf++)
                    zz += fast_exp(acc[mf][nf][e] - mx) + fast_exp(acc[mf][nf][e + 2] - mx);
                cm[nf * 2 + e] = mx;
                cz[nf * 2 + e] = zz;
            }
        }
#pragma unroll
        for (int off = 4; off < 32; off <<= 1) {
#pragma unroll
            for (int c = 0; c < 8; c++) {
                const float om = __shfl_xor_sync(0xffffffff, cm[c], off);
                const float oz = __shfl_xor_sync(0xffffffff, cz[c], off);
                const float mn = fmaxf(cm[c], om);
                cz[c] = cz[c] * fast_exp(cm[c] - mn) + oz * fast_exp(om - mn);
                cm[c] = mn;
            }
        }
        if ((lid >> 2) == 0) {
#pragma unroll
            for (int nf = 0; nf < 4; nf++)
#pragma unroll
                for (int e = 0; e < 2; e++) {
                    const int col = wn * 32 + nf * 8 + (lid & 3) * 2 + e;
                    st[(wm * 128 + col) * 2 + 0] = cm[nf * 2 + e];
                    st[(wm * 128 + col) * 2 + 1] = cz[nf * 2 + e];
                }
        }
        __syncthreads();

        float mcol[8];
#pragma unroll
        for (int nf = 0; nf < 4; nf++)
#pragma unroll
            for (int e = 0; e < 2; e++) {
                const int col = wn * 32 + nf * 8 + (lid & 3) * 2 + e;
                mcol[nf * 2 + e] = fmaxf(st[col * 2], st[(128 + col) * 2]);
            }

#pragma unroll
        for (int mf = 0; mf < 4; mf++) {
#pragma unroll
            for (int nf = 0; nf < 4; nf++) {
                const int m = m0 + wm * 64 + mf * 16 + (lid >> 2);
                const int n = n0 + wn * 32 + nf * 8 + (lid & 3) * 2;
                const float m0c = mcol[nf * 2], m1c = mcol[nf * 2 + 1];
                const __half e0 = __float2half_rn(fast_exp(acc[mf][nf][0] - m0c));
                const __half e1 = __float2half_rn(fast_exp(acc[mf][nf][1] - m1c));
                const __half e2 = __float2half_rn(fast_exp(acc[mf][nf][2] - m0c));
                const __half e3 = __float2half_rn(fast_exp(acc[mf][nf][3] - m1c));
                *(__half2*)(Eh + (size_t)m * ldc + n)       = __halves2half2(e0, e1);
                *(__half2*)(Eh + (size_t)(m + 8) * ldc + n) = __halves2half2(e2, e3);
            }
        }

        if (tid < 128) {
            const float m0v = st[tid * 2],         z0v = st[tid * 2 + 1];
            const float m1v = st[(128 + tid) * 2], z1v = st[(128 + tid) * 2 + 1];
            const float mn = fmaxf(m0v, m1v);
            const float zz = z0v * fast_exp(m0v - mn) + z1v * fast_exp(m1v - mn);
            const size_t o = ((size_t)blockIdx.y * BATCH + blockIdx.z) * SEQ + n0 + tid;
            g_cm[o] = mn;
            g_cz[o] = zz;
        }

        // ---- fused f-combine: last CTA of this column group computes f ----
        __threadfence();
        __syncthreads();
        __shared__ int s_last;
        if (tid == 0) {
            const int grp = blockIdx.z * NTILE + blockIdx.x;
            s_last = (atomicAdd(&g_cnt[grp], 1) == NTILE - 1) ? 1 : 0;
        }
        __syncthreads();
        if (s_last && tid < 128) {
            __threadfence();
            const int k = n0 + tid;
            const int b = blockIdx.z;
            float m = NEG_INF;
#pragma unroll
            for (int t = 0; t < NTILE; t++)
                m = fmaxf(m, __ldcg(&g_cm[((size_t)t * BATCH + b) * SEQ + k]));
            float zz = 0.f;
#pragma unroll
            for (int t = 0; t < NTILE; t++) {
                const size_t o = ((size_t)t * BATCH + b) * SEQ + k;
                zz += __ldcg(&g_cz[o]) * fast_exp(__ldcg(&g_cm[o]) - m);
            }
            const float rz = 1.0f / zz;
#pragma unroll
            for (int t = 0; t < NTILE; t++) {
                const size_t o = ((size_t)t * BATCH + b) * SEQ + k;
                g_f[((size_t)b * NTILE + t) * SEQ + k] =
                    __float2half_rn(fast_exp(__ldcg(&g_cm[o]) - m) * rz);
            }
        }
        return;
    }

#pragma unroll
    for (int mf = 0; mf < 4; mf++) {
#pragma unroll
        for (int nf = 0; nf < 4; nf++) {
            const int m = m0 + wm * 64 + mf * 16 + (lid >> 2);
            const int n = n0 + wn * 32 + nf * 8 + (lid & 3) * 2;
            float v0 = acc[mf][nf][0], v1 = acc[mf][nf][1];
            float v2 = acc[mf][nf][2], v3 = acc[mf][nf][3];
            if (EPI == 4) {
                const float b0 = bias[n], b1 = bias[n + 1];
                v0 += b0; v1 += b1; v2 += b0; v3 += b1;
            }
            if (EPI == 0) {
                *(float2*)(C + (size_t)m * ldc + n)       = make_float2(v0, v1);
                *(float2*)(C + (size_t)(m + 8) * ldc + n) = make_float2(v2, v3);
            } else {  // EPI 4
                const __half h0 = __float2half_rn(v0), h1 = __float2half_rn(v1);
                const __half h2 = __float2half_rn(v2), h3 = __float2half_rn(v3);
                if (z < 2) {
                    __half* Ch = (z == 0) ? g_Qh : g_Kh;
                    __half* Cl = (z == 0) ? g_Ql : g_Kl;
                    const __half l0 = __float2half_rn(v0 - __half2float(h0));
                    const __half l1 = __float2half_rn(v1 - __half2float(h1));
                    const __half l2 = __float2half_rn(v2 - __half2float(h2));
                    const __half l3 = __float2half_rn(v3 - __half2float(h3));
                    *(__half2*)(Ch + (size_t)m * DIM + n)       = __halves2half2(h0, h1);
                    *(__half2*)(Ch + (size_t)(m + 8) * DIM + n) = __halves2half2(h2, h3);
                    *(__half2*)(Cl + (size_t)m * DIM + n)       = __halves2half2(l0, l1);
                    *(__half2*)(Cl + (size_t)(m + 8) * DIM + n) = __halves2half2(l2, l3);
                } else {
                    g_Vth[(size_t)n * MTOT + m]           = h0;
                    g_Vth[(size_t)(n + 1) * MTOT + m]     = h1;
                    g_Vth[(size_t)n * MTOT + m + 8]       = h2;
                    g_Vth[(size_t)(n + 1) * MTOT + m + 8] = h3;
                }
            }
        }
    }
}

// ---------------------------------------------------------------------------
// One fused split pass: X then Wq, Wk, Wv; block 0 also resets tickets.
#define XN4 (MTOT * DIM / 4)
#define WN4 (WSZ / 4)

__global__ void __launch_bounds__(256)
split_all(const float* __restrict__ X, const float* __restrict__ Wq,
          const float* __restrict__ Wk, const float* __restrict__ Wv)
{
    if (blockIdx.x == 0 && threadIdx.x < BATCH * NTILE)
        g_cnt[threadIdx.x] = 0;

    const int i = blockIdx.x * 256 + threadIdx.x;
    const float* src;
    __half *h, *l;
    int j;
    if (i < XN4)                { src = X;  h = g_Xh;    l = g_Xl;    j = i; }
    else if (i < XN4 + WN4)     { src = Wq; h = g_Wh[0]; l = g_Wl[0]; j = i - XN4; }
    else if (i < XN4 + 2 * WN4) { src = Wk; h = g_Wh[1]; l = g_Wl[1]; j = i - XN4 - WN4; }
    else if (i < XN4 + 3 * WN4) { src = Wv; h = g_Wh[2]; l = g_Wl[2]; j = i - XN4 - 2 * WN4; }
    else return;

    const float4 v = ((const float4*)src)[j];
    float vv[4] = {v.x, v.y, v.z, v.w};
    __half hh[4], ll[4];
#pragma unroll
    for (int e = 0; e < 4; e++) {
        hh[e] = __float2half_rn(vv[e]);
        ll[e] = __float2half_rn(vv[e] - __half2float(hh[e]));
    }
    ((__half2*)h)[j * 2]     = __halves2half2(hh[0], hh[1]);
    ((__half2*)h)[j * 2 + 1] = __halves2half2(hh[2], hh[3]);
    ((__half2*)l)[j * 2]     = __halves2half2(ll[0], ll[1]);
    ((__half2*)l)[j * 2 + 1] = __halves2half2(ll[2], ll[3]);
}

// ---------------------------------------------------------------------------
extern "C" void kernel_launch(void* const* d_in, const int* in_sizes, int n_in,
                              void* d_out, int out_size)
{
    const float* X  = (const float*)d_in[0];
    const float* Wq = (const float*)d_in[1];
    const float* bq = (const float*)d_in[2];
    const float* Wk = (const float*)d_in[3];
    const float* bk = (const float*)d_in[4];
    const float* Wv = (const float*)d_in[5];
    const float* bv = (const float*)d_in[6];
    float* out = (float*)d_out;

    __half *pXh, *pXl, *pWh, *pWl, *pQh, *pQl, *pKh, *pKl, *pVth, *pE, *pF;
    cudaGetSymbolAddress((void**)&pXh,  g_Xh);
    cudaGetSymbolAddress((void**)&pXl,  g_Xl);
    cudaGetSymbolAddress((void**)&pWh,  g_Wh);
    cudaGetSymbolAddress((void**)&pWl,  g_Wl);
    cudaGetSymbolAddress((void**)&pQh,  g_Qh);
    cudaGetSymbolAddress((void**)&pQl,  g_Ql);
    cudaGetSymbolAddress((void**)&pKh,  g_Kh);
    cudaGetSymbolAddress((void**)&pKl,  g_Kl);
    cudaGetSymbolAddress((void**)&pVth, g_Vth);
    cudaGetSymbolAddress((void**)&pE,   g_E);
    cudaGetSymbolAddress((void**)&pF,   g_f);

    // smem: QKV/S = 3 x 32KB ring = 98304; PV = 3 x 16KB ring + 8KB f = 57344
    cudaFuncSetAttribute((const void*)gemm_hl<4,1,1,0>, cudaFuncAttributeMaxDynamicSharedMemorySize, 98304);
    cudaFuncSetAttribute((const void*)gemm_hl<3,1,1,0>, cudaFuncAttributeMaxDynamicSharedMemorySize, 98304);
    cudaFuncSetAttribute((const void*)gemm_hl<0,0,0,1>, cudaFuncAttributeMaxDynamicSharedMemorySize, 57344);

    const dim3 blk(TCT);

    // fused input splits (X + Wq + Wk + Wv) + ticket reset
    const int TOT4 = XN4 + 3 * WN4;
    split_all<<<(TOT4 + 255) / 256, 256>>>(X, Wq, Wk, Wv);

    // fused QKV projections (K=512): one launch, z selects q/k/v
    const dim3 gQKV(DIM / 128, MTOT / 128, 3);
    gemm_hl<4,1,1,0><<<gQKV, blk, 98304>>>(pXh, pXl, pWh, pWl, bq, bk, bv,
                                           nullptr, nullptr, nullptr,
                                           DIM, DIM, DIM, DIM, 0, 0, 0);

    // S-GEMM per batch (K=512): E' fp16 + stats + fused f-combine
    const dim3 gS(SEQ / 128, SEQ / 128, BATCH);
    gemm_hl<3,1,1,0><<<gS, blk, 98304>>>(pQh, pQl, pKh, pKl,
                                         nullptr, nullptr, nullptr,
                                         nullptr, pE, nullptr,
                                         DIM, DIM, DIM, SEQ,
                                         (long)SEQ * DIM, (long)SEQ * DIM,
                                         (long)SEQ * SEQ);

    // O = E' (f·V) per batch (K=4096), single MMA + B-side f multiply
    const dim3 gPV(DIM / 128, SEQ / 128, BATCH);
    gemm_hl<0,0,0,1><<<gPV, blk, 57344>>>(pE, nullptr, pVth, nullptr,
                                          nullptr, nullptr, nullptr,
                                          out, nullptr, pF,
                                          SEQ, SEQ, MTOT, DIM,
                                          (long)SEQ * SEQ, SEQ, (long)SEQ * DIM);
}

// round 17
// speedup vs baseline: 1.1298x; 1.0263x over previous
#include <cuda_runtime.h>
#include <cuda_fp16.h>
#include <math.h>
#include <stdint.h>

#define BATCH 4
#define SEQ   4096
#define DIM   512
#define MTOT  (BATCH * SEQ)
#define NTILE (SEQ / 128)
#define WSZ   (DIM * DIM)
#define NEG_INF __int_as_float(0xff800000)

// ---------------- scratch (static device globals; no allocation) ------------
__device__ __half g_Xh[(size_t)MTOT * DIM],  g_Xl[(size_t)MTOT * DIM];
__device__ __half g_Wh[3][WSZ],              g_Wl[3][WSZ];
__device__ __half g_Qh[(size_t)MTOT * DIM],  g_Ql[(size_t)MTOT * DIM];
__device__ __half g_Kh[(size_t)MTOT * DIM],  g_Kl[(size_t)MTOT * DIM];
__device__ __half g_Vth[(size_t)DIM * MTOT];               // V^T hi plane only
__device__ __half g_E [(size_t)BATCH * SEQ * SEQ];         // exp(S - m_tile), fp16
__device__ float  g_cm[(size_t)NTILE * BATCH * SEQ];       // per-tile col max
__device__ float  g_cz[(size_t)NTILE * BATCH * SEQ];       // per-tile col sumexp
__device__ __half g_f [(size_t)BATCH * NTILE * SEQ];       // exp(m_tile-m)/Z
__device__ int    g_cnt[BATCH * NTILE];                    // column-group tickets

// ---------------- fast exp on the FMA pipe -----------------------------------
__device__ __forceinline__ float fast_exp(float x) {
    x = fmaxf(x, -80.0f);
    const float y  = x * 1.4426950408889634f;
    const float t  = y + 12582912.0f;
    const int   ni = __float_as_int(t) - 0x4B400000;
    const float f  = y - (t - 12582912.0f);
    float p = 1.3333558146e-3f;
    p = fmaf(p, f, 9.6181291076e-3f);
    p = fmaf(p, f, 5.5504108664e-2f);
    p = fmaf(p, f, 2.4022650696e-1f);
    p = fmaf(p, f, 6.9314718056e-1f);
    p = fmaf(p, f, 1.0f);
    return __int_as_float(__float_as_int(p) + (ni << 23));
}

// ============================ PTX helpers ===================================
__device__ __forceinline__ uint32_t smem_u32(const void* p) {
    uint32_t a;
    asm("{ .reg .u64 t; cvta.to.shared.u64 t, %1; cvt.u32.u64 %0, t; }"
        : "=r"(a) : "l"(p));
    return a;
}
template<int N> __device__ __forceinline__ void cp_wait() {
    asm volatile("cp.async.wait_group %0;" :: "n"(N) : "memory");
}
__device__ __forceinline__ void cp_commit() {
    asm volatile("cp.async.commit_group;" ::: "memory");
}
__device__ __forceinline__ void cp16(uint32_t dst, const void* src) {
    asm volatile("cp.async.cg.shared.global [%0], [%1], 16;"
                 :: "r"(dst), "l"(src) : "memory");
}
__device__ __forceinline__ void ldsm4(uint32_t* r, uint32_t a) {
    asm volatile("ldmatrix.sync.aligned.m8n8.x4.shared.b16 {%0,%1,%2,%3}, [%4];"
                 : "=r"(r[0]), "=r"(r[1]), "=r"(r[2]), "=r"(r[3]) : "r"(a));
}
__device__ __forceinline__ void mma16816(float* d, const uint32_t* a,
                                         uint32_t b0, uint32_t b1) {
    asm volatile("mma.sync.aligned.m16n8k16.row.col.f32.f16.f16.f32 "
                 "{%0,%1,%2,%3},{%4,%5,%6,%7},{%8,%9},{%0,%1,%2,%3};"
                 : "+f"(d[0]), "+f"(d[1]), "+f"(d[2]), "+f"(d[3])
                 : "r"(a[0]), "r"(a[1]), "r"(a[2]), "r"(a[3]), "r"(b0), "r"(b1));
}
__device__ __forceinline__ uint32_t hmul2u(uint32_t a, uint32_t b) {
    const __half2 r = __hmul2(*(const __half2*)&a, *(const __half2*)&b);
    return *(const uint32_t*)&r;
}

// ============================ GEMM (hi/lo fp16) ==============================
// BK=32 path (QKV + S). 128x128 tiles; 3-stage ring, 1 sync/stage.
// EPI 3: fp16 E' + stats + fused f-combine via ticket            (S)
// EPI 4: fused QKV: z selects W plane/bias; z<2 hi/lo, z=2 V^T
#define TCT 256

template<int EPI>
__global__ void __launch_bounds__(TCT, 2)
gemm_hl(const __half* __restrict__ Ah, const __half* __restrict__ Al,
        const __half* __restrict__ Bh, const __half* __restrict__ Bl,
        const float* __restrict__ bias0, const float* __restrict__ bias1,
        const float* __restrict__ bias2,
        __half* __restrict__ Eh,
        int K, int lda, int ldb, int ldc,
        long sA, long sB, long sC)
{
    constexpr int OFF_AL = 8192;
    constexpr int OFF_BH = 16384;
    constexpr int OFF_BL = 24576;
    constexpr int STG    = 32768;

    extern __shared__ __align__(128) char smem[];
    const uint32_t sb = smem_u32(smem);

    const int tid = threadIdx.x;
    const int lid = tid & 31;
    const int wid = tid >> 5;
    const int wm  = wid >> 2;
    const int wn  = wid & 3;

    const long z = blockIdx.z;
    const float* bias = bias0;
    if (EPI == 4) {
        Bh += z * WSZ; Bl += z * WSZ;
        bias = (z == 0) ? bias0 : (z == 1) ? bias1 : bias2;
    } else {
        Ah += z * sA; Al += z * sA;
        Bh += z * sB; Bl += z * sB;
        Eh += z * sC;
    }

    const int m0 = blockIdx.y * 128;
    const int n0 = blockIdx.x * 128;

    const int nstage = K / 32;

    auto issue = [&](int s, int buf) {
        const uint32_t base = sb + buf * STG;
        const int k0 = s * 32;
#pragma unroll
        for (int i = 0; i < 2; i++) {
            const int chunk = i * 256 + tid;
            const int r = chunk >> 2;
            const int c = chunk & 3;
            const uint32_t doff = r * 64 + ((c ^ ((r + (r >> 2)) & 3)) * 16);
            const size_t ga = (size_t)(m0 + r) * lda + k0 + c * 8;
            const size_t gb = (size_t)(n0 + r) * ldb + k0 + c * 8;
            cp16(base + doff, Ah + ga);
            cp16(base + OFF_AL + doff, Al + ga);
            cp16(base + OFF_BH + doff, Bh + gb);
            cp16(base + OFF_BL + doff, Bl + gb);
        }
        cp_commit();
    };

    float acc[4][4][4];
#pragma unroll
    for (int a = 0; a < 4; a++)
#pragma unroll
        for (int b = 0; b < 4; b++)
#pragma unroll
            for (int c = 0; c < 4; c++) acc[a][b][c] = 0.f;

    const int sub   = lid >> 3;
    const int lane7 = lid & 7;
    const int rA = wm * 64 + (sub & 1) * 8 + lane7;
    const int rB = wn * 32 + (sub & 1) * 8 + lane7;
    const int cs = sub >> 1;
    const int swA = (rA + (rA >> 2)) & 3;
    const int swB = (rB + (rB >> 2)) & 3;

    issue(0, 0);
    issue(1, 1);

    int buf = 0, nbuf = 2;
    for (int s = 0; s < nstage; s++) {
        if (s + 1 < nstage) cp_wait<1>(); else cp_wait<0>();
        __syncthreads();

        const uint32_t stg = sb + buf * STG;
#pragma unroll
        for (int kt = 0; kt < 2; kt++) {
            const int ch = 2 * kt + cs;
            const uint32_t aoff = ((ch ^ swA) * 16);
            const uint32_t boff = ((ch ^ swB) * 16);

            uint32_t aH[4][4], bH[2][4];
#pragma unroll
            for (int mf = 0; mf < 4; mf++)
                ldsm4(aH[mf], stg + (rA + mf * 16) * 64 + aoff);
#pragma unroll
            for (int bg = 0; bg < 2; bg++)
                ldsm4(bH[bg], stg + OFF_BH + (rB + bg * 16) * 64 + boff);

#pragma unroll
            for (int mf = 0; mf < 4; mf++)
#pragma unroll
                for (int nf = 0; nf < 4; nf++)
                    mma16816(acc[mf][nf], aH[mf],
                             bH[nf >> 1][nf & 1], bH[nf >> 1][(nf & 1) + 2]);

            {
                uint32_t aL[4][4];
#pragma unroll
                for (int mf = 0; mf < 4; mf++)
                    ldsm4(aL[mf], stg + OFF_AL + (rA + mf * 16) * 64 + aoff);
#pragma unroll
                for (int mf = 0; mf < 4; mf++)
#pragma unroll
                    for (int nf = 0; nf < 4; nf++)
                        mma16816(acc[mf][nf], aL[mf],
                                 bH[nf >> 1][nf & 1], bH[nf >> 1][(nf & 1) + 2]);
            }
            {
                uint32_t bL[2][4];
#pragma unroll
                for (int bg = 0; bg < 2; bg++)
                    ldsm4(bL[bg], stg + OFF_BL + (rB + bg * 16) * 64 + boff);
#pragma unroll
                for (int mf = 0; mf < 4; mf++)
#pragma unroll
                    for (int nf = 0; nf < 4; nf++)
                        mma16816(acc[mf][nf], aH[mf],
                                 bL[nf >> 1][nf & 1], bL[nf >> 1][(nf & 1) + 2]);
            }
        }

        if (s + 2 < nstage) issue(s + 2, nbuf);
        buf  = (buf  == 2) ? 0 : buf + 1;
        nbuf = (nbuf == 2) ? 0 : nbuf + 1;
    }

    // -------------------------- epilogue ------------------------------------
    if (EPI == 3) {
        __syncthreads();
        float* st = (float*)smem;

        float cm[8], cz[8];
#pragma unroll
        for (int nf = 0; nf < 4; nf++) {
#pragma unroll
            for (int e = 0; e < 2; e++) {
                float mx = NEG_INF;
#pragma unroll
                for (int mf = 0; mf < 4; mf++) {
                    mx = fmaxf(mx, acc[mf][nf][e]);
                    mx = fmaxf(mx, acc[mf][nf][e + 2]);
                }
                float zz = 0.f;
#pragma unroll
                for (int mf = 0; mf < 4; mf++)
                    zz += fast_exp(acc[mf][nf][e] - mx) + fast_exp(acc[mf][nf][e + 2] - mx);
                cm[nf * 2 + e] = mx;
                cz[nf * 2 + e] = zz;
            }
        }
#pragma unroll
        for (int off = 4; off < 32; off <<= 1) {
#pragma unroll
            for (int c = 0; c < 8; c++) {
                const float om = __shfl_xor_sync(0xffffffff, cm[c], off);
                const float oz = __shfl_xor_sync(0xffffffff, cz[c], off);
                const float mn = fmaxf(cm[c], om);
                cz[c] = cz[c] * fast_exp(cm[c] - mn) + oz * fast_exp(om - mn);
                cm[c] = mn;
            }
        }
        if ((lid >> 2) == 0) {
#pragma unroll
            for (int nf = 0; nf < 4; nf++)
#pragma unroll
                for (int e = 0; e < 2; e++) {
                    const int col = wn * 32 + nf * 8 + (lid & 3) * 2 + e;
                    st[(wm * 128 + col) * 2 + 0] = cm[nf * 2 + e];
                    st[(wm * 128 + col) * 2 + 1] = cz[nf * 2 + e];
                }
        }
        __syncthreads();

        float mcol[8];
#pragma unroll
        for (int nf = 0; nf < 4; nf++)
#pragma unroll
            for (int e = 0; e < 2; e++) {
                const int col = wn * 32 + nf * 8 + (lid & 3) * 2 + e;
                mcol[nf * 2 + e] = fmaxf(st[col * 2], st[(128 + col) * 2]);
            }

#pragma unroll
        for (int mf = 0; mf < 4; mf++) {
#pragma unroll
            for (int nf = 0; nf < 4; nf++) {
                const int m = m0 + wm * 64 + mf * 16 + (lid >> 2);
                const int n = n0 + wn * 32 + nf * 8 + (lid & 3) * 2;
                const float m0c = mcol[nf * 2], m1c = mcol[nf * 2 + 1];
                const __half e0 = __float2half_rn(fast_exp(acc[mf][nf][0] - m0c));
                const __half e1 = __float2half_rn(fast_exp(acc[mf][nf][1] - m1c));
                const __half e2 = __float2half_rn(fast_exp(acc[mf][nf][2] - m0c));
                const __half e3 = __float2half_rn(fast_exp(acc[mf][nf][3] - m1c));
                *(__half2*)(Eh + (size_t)m * ldc + n)       = __halves2half2(e0, e1);
                *(__half2*)(Eh + (size_t)(m + 8) * ldc + n) = __halves2half2(e2, e3);
            }
        }

        if (tid < 128) {
            const float m0v = st[tid * 2],         z0v = st[tid * 2 + 1];
            const float m1v = st[(128 + tid) * 2], z1v = st[(128 + tid) * 2 + 1];
            const float mn = fmaxf(m0v, m1v);
            const float zz = z0v * fast_exp(m0v - mn) + z1v * fast_exp(m1v - mn);
            const size_t o = ((size_t)blockIdx.y * BATCH + blockIdx.z) * SEQ + n0 + tid;
            g_cm[o] = mn;
            g_cz[o] = zz;
        }

        __threadfence();
        __syncthreads();
        __shared__ int s_last;
        if (tid == 0) {
            const int grp = blockIdx.z * NTILE + blockIdx.x;
            s_last = (atomicAdd(&g_cnt[grp], 1) == NTILE - 1) ? 1 : 0;
        }
        __syncthreads();
        if (s_last && tid < 128) {
            __threadfence();
            const int k = n0 + tid;
            const int b = blockIdx.z;
            float m = NEG_INF;
#pragma unroll
            for (int t = 0; t < NTILE; t++)
                m = fmaxf(m, __ldcg(&g_cm[((size_t)t * BATCH + b) * SEQ + k]));
            float zz = 0.f;
#pragma unroll
            for (int t = 0; t < NTILE; t++) {
                const size_t o = ((size_t)t * BATCH + b) * SEQ + k;
                zz += __ldcg(&g_cz[o]) * fast_exp(__ldcg(&g_cm[o]) - m);
            }
            const float rz = 1.0f / zz;
#pragma unroll
            for (int t = 0; t < NTILE; t++) {
                const size_t o = ((size_t)t * BATCH + b) * SEQ + k;
                g_f[((size_t)b * NTILE + t) * SEQ + k] =
                    __float2half_rn(fast_exp(__ldcg(&g_cm[o]) - m) * rz);
            }
        }
        return;
    }

    // EPI 4 epilogue
#pragma unroll
    for (int mf = 0; mf < 4; mf++) {
#pragma unroll
        for (int nf = 0; nf < 4; nf++) {
            const int m = m0 + wm * 64 + mf * 16 + (lid >> 2);
            const int n = n0 + wn * 32 + nf * 8 + (lid & 3) * 2;
            const float b0 = bias[n], b1 = bias[n + 1];
            const float v0 = acc[mf][nf][0] + b0, v1 = acc[mf][nf][1] + b1;
            const float v2 = acc[mf][nf][2] + b0, v3 = acc[mf][nf][3] + b1;
            const __half h0 = __float2half_rn(v0), h1 = __float2half_rn(v1);
            const __half h2 = __float2half_rn(v2), h3 = __float2half_rn(v3);
            if (z < 2) {
                __half* Ch = (z == 0) ? g_Qh : g_Kh;
                __half* Cl = (z == 0) ? g_Ql : g_Kl;
                const __half l0 = __float2half_rn(v0 - __half2float(h0));
                const __half l1 = __float2half_rn(v1 - __half2float(h1));
                const __half l2 = __float2half_rn(v2 - __half2float(h2));
                const __half l3 = __float2half_rn(v3 - __half2float(h3));
                *(__half2*)(Ch + (size_t)m * DIM + n)       = __halves2half2(h0, h1);
                *(__half2*)(Ch + (size_t)(m + 8) * DIM + n) = __halves2half2(h2, h3);
                *(__half2*)(Cl + (size_t)m * DIM + n)       = __halves2half2(l0, l1);
                *(__half2*)(Cl + (size_t)(m + 8) * DIM + n) = __halves2half2(l2, l3);
            } else {
                g_Vth[(size_t)n * MTOT + m]           = h0;
                g_Vth[(size_t)(n + 1) * MTOT + m]     = h1;
                g_Vth[(size_t)n * MTOT + m + 8]       = h2;
                g_Vth[(size_t)(n + 1) * MTOT + m + 8] = h3;
            }
        }
    }
}

// ============================ PV GEMM (BK=64, 3-stage ring) ==================
// O[m,n] = sum_k E[m,k] * (f[k]*Vt[n,k]);  128x128 tile, rows 128B SW128.
#define PVSTG 32768          // A 16KB + B 16KB per stage
#define PVF_OFF (3 * PVSTG)  // 8KB f table after ring

__global__ void __launch_bounds__(TCT, 2)
pv_gemm(const __half* __restrict__ E, const __half* __restrict__ Vt,
        const __half* __restrict__ fTab, float* __restrict__ O)
{
    extern __shared__ __align__(128) char smem[];
    const uint32_t sb = smem_u32(smem);

    const int tid = threadIdx.x;
    const int lid = tid & 31;
    const int wid = tid >> 5;
    const int wm  = wid >> 2;
    const int wn  = wid & 3;

    const long z = blockIdx.z;
    E  += z * (long)SEQ * SEQ;
    O  += z * (long)SEQ * DIM;
    const long vcol = z * SEQ;

    const int m0 = blockIdx.y * 128;
    const int n0 = blockIdx.x * 128;

    // preload f row (512 cols x 16B = 8KB)
    {
        const __half* fB = fTab + ((size_t)z * NTILE + blockIdx.y) * SEQ;
#pragma unroll
        for (int i = 0; i < 2; i++) {
            const int c = i * 256 + tid;
            *(uint4*)(smem + PVF_OFF + c * 16) = *(const uint4*)(fB + c * 8);
        }
    }

    const int nstage = SEQ / 64;   // 64

    auto issue = [&](int s, int buf) {
        const uint32_t base = sb + buf * PVSTG;
        const int k0 = s * 64;
#pragma unroll
        for (int i = 0; i < 4; i++) {
            const int chunk = i * 256 + tid;
            const int r = chunk >> 3;          // 0..127
            const int c = chunk & 7;           // 0..7
            const uint32_t doff = r * 128 + ((c ^ (r & 7)) * 16);
            cp16(base + doff,         E  + (size_t)(m0 + r) * SEQ + k0 + c * 8);
            cp16(base + 16384 + doff, Vt + (size_t)(n0 + r) * MTOT + vcol + k0 + c * 8);
        }
        cp_commit();
    };

    float acc[4][4][4];
#pragma unroll
    for (int a = 0; a < 4; a++)
#pragma unroll
        for (int b = 0; b < 4; b++)
#pragma unroll
            for (int c = 0; c < 4; c++) acc[a][b][c] = 0.f;

    const int sub   = lid >> 3;
    const int lane7 = lid & 7;
    const int rA = wm * 64 + (sub & 1) * 8 + lane7;
    const int rB = wn * 32 + (sub & 1) * 8 + lane7;
    const int cs = sub >> 1;
    const int swA = rA & 7;
    const int swB = rB & 7;

    issue(0, 0);
    issue(1, 1);

    int buf = 0, nbuf = 2;
    for (int s = 0; s < nstage; s++) {
        if (s + 1 < nstage) cp_wait<1>(); else cp_wait<0>();
        __syncthreads();

        const uint32_t stg = sb + buf * PVSTG;
#pragma unroll
        for (int kt = 0; kt < 4; kt++) {
            const int ch = 2 * kt + cs;        // 0..7
            const uint32_t aoff = ((ch ^ swA) * 16);
            const uint32_t boff = ((ch ^ swB) * 16);

            uint32_t aH[4][4], bH[2][4];
#pragma unroll
            for (int mf = 0; mf < 4; mf++)
                ldsm4(aH[mf], stg + (rA + mf * 16) * 128 + aoff);
#pragma unroll
            for (int bg = 0; bg < 2; bg++)
                ldsm4(bH[bg], stg + 16384 + (rB + bg * 16) * 128 + boff);

            // scale B k-slices by f
            {
                const int kb = s * 64 + kt * 16 + (lid & 3) * 2;
                const uint32_t flo = *(const uint32_t*)(smem + PVF_OFF + kb * 2);
                const uint32_t fhi = *(const uint32_t*)(smem + PVF_OFF + kb * 2 + 16);
#pragma unroll
                for (int bg = 0; bg < 2; bg++) {
                    bH[bg][0] = hmul2u(bH[bg][0], flo);
                    bH[bg][1] = hmul2u(bH[bg][1], flo);
                    bH[bg][2] = hmul2u(bH[bg][2], fhi);
                    bH[bg][3] = hmul2u(bH[bg][3], fhi);
                }
            }

#pragma unroll
            for (int mf = 0; mf < 4; mf++)
#pragma unroll
                for (int nf = 0; nf < 4; nf++)
                    mma16816(acc[mf][nf], aH[mf],
                             bH[nf >> 1][nf & 1], bH[nf >> 1][(nf & 1) + 2]);
        }

        if (s + 2 < nstage) issue(s + 2, nbuf);
        buf  = (buf  == 2) ? 0 : buf + 1;
        nbuf = (nbuf == 2) ? 0 : nbuf + 1;
    }

#pragma unroll
    for (int mf = 0; mf < 4; mf++)
#pragma unroll
        for (int nf = 0; nf < 4; nf++) {
            const int m = m0 + wm * 64 + mf * 16 + (lid >> 2);
            const int n = n0 + wn * 32 + nf * 8 + (lid & 3) * 2;
            *(float2*)(O + (size_t)m * DIM + n) =
                make_float2(acc[mf][nf][0], acc[mf][nf][1]);
            *(float2*)(O + (size_t)(m + 8) * DIM + n) =
                make_float2(acc[mf][nf][2], acc[mf][nf][3]);
        }
}

// ---------------------------------------------------------------------------
// One fused split pass: X then Wq, Wk, Wv; block 0 also resets tickets.
#define XN4 (MTOT * DIM / 4)
#define WN4 (WSZ / 4)

__global__ void __launch_bounds__(256)
split_all(const float* __restrict__ X, const float* __restrict__ Wq,
          const float* __restrict__ Wk, const float* __restrict__ Wv)
{
    if (blockIdx.x == 0 && threadIdx.x < BATCH * NTILE)
        g_cnt[threadIdx.x] = 0;

    const int i = blockIdx.x * 256 + threadIdx.x;
    const float* src;
    __half *h, *l;
    int j;
    if (i < XN4)                { src = X;  h = g_Xh;    l = g_Xl;    j = i; }
    else if (i < XN4 + WN4)     { src = Wq; h = g_Wh[0]; l = g_Wl[0]; j = i - XN4; }
    else if (i < XN4 + 2 * WN4) { src = Wk; h = g_Wh[1]; l = g_Wl[1]; j = i - XN4 - WN4; }
    else if (i < XN4 + 3 * WN4) { src = Wv; h = g_Wh[2]; l = g_Wl[2]; j = i - XN4 - 2 * WN4; }
    else return;

    const float4 v = ((const float4*)src)[j];
    float vv[4] = {v.x, v.y, v.z, v.w};
    __half hh[4], ll[4];
#pragma unroll
    for (int e = 0; e < 4; e++) {
        hh[e] = __float2half_rn(vv[e]);
        ll[e] = __float2half_rn(vv[e] - __half2float(hh[e]));
    }
    ((__half2*)h)[j * 2]     = __halves2half2(hh[0], hh[1]);
    ((__half2*)h)[j * 2 + 1] = __halves2half2(hh[2], hh[3]);
    ((__half2*)l)[j * 2]     = __halves2half2(ll[0], ll[1]);
    ((__half2*)l)[j * 2 + 1] = __halves2half2(ll[2], ll[3]);
}

// ---------------------------------------------------------------------------
extern "C" void kernel_launch(void* const* d_in, const int* in_sizes, int n_in,
                              void* d_out, int out_size)
{
    const float* X  = (const float*)d_in[0];
    const float* Wq = (const float*)d_in[1];
    const float* bq = (const float*)d_in[2];
    const float* Wk = (const float*)d_in[3];
    const float* bk = (const float*)d_in[4];
    const float* Wv = (const float*)d_in[5];
    const float* bv = (const float*)d_in[6];
    float* out = (float*)d_out;

    __half *pXh, *pXl, *pWh, *pWl, *pQh, *pQl, *pKh, *pKl, *pVth, *pE, *pF;
    cudaGetSymbolAddress((void**)&pXh,  g_Xh);
    cudaGetSymbolAddress((void**)&pXl,  g_Xl);
    cudaGetSymbolAddress((void**)&pWh,  g_Wh);
    cudaGetSymbolAddress((void**)&pWl,  g_Wl);
    cudaGetSymbolAddress((void**)&pQh,  g_Qh);
    cudaGetSymbolAddress((void**)&pQl,  g_Ql);
    cudaGetSymbolAddress((void**)&pKh,  g_Kh);
    cudaGetSymbolAddress((void**)&pKl,  g_Kl);
    cudaGetSymbolAddress((void**)&pVth, g_Vth);
    cudaGetSymbolAddress((void**)&pE,   g_E);
    cudaGetSymbolAddress((void**)&pF,   g_f);

    // smem: QKV/S = 3 x 32KB = 98304; PV = 3 x 32KB + 8KB f = 106496
    cudaFuncSetAttribute((const void*)gemm_hl<4>, cudaFuncAttributeMaxDynamicSharedMemorySize, 98304);
    cudaFuncSetAttribute((const void*)gemm_hl<3>, cudaFuncAttributeMaxDynamicSharedMemorySize, 98304);
    cudaFuncSetAttribute((const void*)pv_gemm,    cudaFuncAttributeMaxDynamicSharedMemorySize, 106496);

    const dim3 blk(TCT);

    // fused input splits (X + Wq + Wk + Wv) + ticket reset
    const int TOT4 = XN4 + 3 * WN4;
    split_all<<<(TOT4 + 255) / 256, 256>>>(X, Wq, Wk, Wv);

    // fused QKV projections (K=512): one launch, z selects q/k/v
    const dim3 gQKV(DIM / 128, MTOT / 128, 3);
    gemm_hl<4><<<gQKV, blk, 98304>>>(pXh, pXl, pWh, pWl, bq, bk, bv,
                                     nullptr, DIM, DIM, DIM, DIM, 0, 0, 0);

    // S-GEMM per batch (K=512): E' fp16 + stats + fused f-combine
    const dim3 gS(SEQ / 128, SEQ / 128, BATCH);
    gemm_hl<3><<<gS, blk, 98304>>>(pQh, pQl, pKh, pKl,
                                   nullptr, nullptr, nullptr,
                                   pE, DIM, DIM, DIM, SEQ,
                                   (long)SEQ * DIM, (long)SEQ * DIM,
                                   (long)SEQ * SEQ);

    // O = E' (f·V) per batch: BK=64 ring, single MMA + B-side f multiply
    const dim3 gPV(DIM / 128, SEQ / 128, BATCH);
    pv_gemm<<<gPV, blk, 106496>>>(pE, pVth, pF, out);
}